// round 14
// baseline (speedup 1.0000x reference)
#include <cuda_runtime.h>
#include <cuda_bf16.h>
#include <math.h>
#include <float.h>
#include <stdint.h>

#define TT     2048
#define HID    4096
#define NHEADS 32
#define NKVH   8
#define HDIM   128
#define QKVO   6144
#define RANK   256
#define NIM    512
#define NMEM   128
#define CACHE_ELEMS (4*64*NKVH*HDIM)

// ---------------- scratch ----------------
__device__ float g_qkv[TT * QKVO];

__device__ __nv_bfloat16 g_hs_hi[TT*HID],    g_hs_lo[TT*HID];
__device__ __nv_bfloat16 g_attn_hi[TT*HID],  g_attn_lo[TT*HID];
__device__ __nv_bfloat16 g_q_hi[TT*HID],     g_q_lo[TT*HID];
__device__ __nv_bfloat16 g_k_hi[TT*NKVH*HDIM], g_k_lo[TT*NKVH*HDIM];
__device__ __nv_bfloat16 g_v_hi[TT*NKVH*HDIM], g_v_lo[TT*NKVH*HDIM];
__device__ __nv_bfloat16 g_tim_hi[NIM*RANK],  g_tim_lo[NIM*RANK];
__device__ __nv_bfloat16 g_tmem_hi[NMEM*RANK], g_tmem_lo[NMEM*RANK];

__device__ __nv_bfloat16 g_wqkv_hi[QKVO*HID], g_wqkv_lo[QKVO*HID];
__device__ __nv_bfloat16 g_wqA_hi[RANK*HID],  g_wqA_lo[RANK*HID];
__device__ __nv_bfloat16 g_wqB_hi[QKVO*RANK], g_wqB_lo[QKVO*RANK];
__device__ __nv_bfloat16 g_wqMA_hi[RANK*HID], g_wqMA_lo[RANK*HID];
__device__ __nv_bfloat16 g_wqMB_hi[QKVO*RANK],g_wqMB_lo[QKVO*RANK];
__device__ __nv_bfloat16 g_wo_hi[HID*HID],    g_wo_lo[HID*HID];
__device__ __nv_bfloat16 g_woA_hi[RANK*HID],  g_woA_lo[RANK*HID];
__device__ __nv_bfloat16 g_woB_hi[HID*RANK],  g_woB_lo[HID*RANK];
__device__ __nv_bfloat16 g_woMA_hi[RANK*HID], g_woMA_lo[RANK*HID];
__device__ __nv_bfloat16 g_woMB_hi[HID*RANK], g_woMB_lo[HID*RANK];

// ---------------- helpers ----------------
__device__ __forceinline__ uint32_t pack_bf16(float x, float y) {
    __nv_bfloat162 t = __floats2bfloat162_rn(x, y);
    return *reinterpret_cast<uint32_t*>(&t);
}
__device__ __forceinline__ void split2(float x, float y, uint32_t& h, uint32_t& l) {
    float hx = __bfloat162float(__float2bfloat16(x));
    float hy = __bfloat162float(__float2bfloat16(y));
    h = pack_bf16(x, y);
    l = pack_bf16(x - hx, y - hy);
}
__device__ __forceinline__ void mma16816(float* c, const uint32_t* a, const uint32_t* b) {
    asm volatile(
        "mma.sync.aligned.m16n8k16.row.col.f32.bf16.bf16.f32 "
        "{%0,%1,%2,%3}, {%4,%5,%6,%7}, {%8,%9}, {%0,%1,%2,%3};\n"
        : "+f"(c[0]), "+f"(c[1]), "+f"(c[2]), "+f"(c[3])
        : "r"(a[0]), "r"(a[1]), "r"(a[2]), "r"(a[3]), "r"(b[0]), "r"(b[1]));
}
__device__ __forceinline__ uint32_t s2u(const void* p) {
    return (uint32_t)__cvta_generic_to_shared(p);
}
__device__ __forceinline__ void cp16(uint32_t saddr, const void* gaddr) {
    asm volatile("cp.async.cg.shared.global [%0], [%1], 16;\n" :: "r"(saddr), "l"(gaddr));
}
#define CP_COMMIT() asm volatile("cp.async.commit_group;\n")
#define CP_WAIT0()  asm volatile("cp.async.wait_group 0;\n")
__device__ __forceinline__ void ldsm4(uint32_t* r, uint32_t saddr) {
    asm volatile("ldmatrix.sync.aligned.m8n8.x4.shared.b16 {%0,%1,%2,%3}, [%4];\n"
        : "=r"(r[0]), "=r"(r[1]), "=r"(r[2]), "=r"(r[3]) : "r"(saddr));
}
__device__ __forceinline__ void ldsm4t(uint32_t* r, uint32_t saddr) {
    asm volatile("ldmatrix.sync.aligned.m8n8.x4.trans.shared.b16 {%0,%1,%2,%3}, [%4];\n"
        : "=r"(r[0]), "=r"(r[1]), "=r"(r[2]), "=r"(r[3]) : "r"(saddr));
}

// ---------------- split conversion ----------------
__global__ void conv_split(const float4* __restrict__ in,
                           __nv_bfloat16* __restrict__ hi,
                           __nv_bfloat16* __restrict__ lo, int n4)
{
    int i = blockIdx.x * blockDim.x + threadIdx.x;
    int stride = gridDim.x * blockDim.x;
    for (; i < n4; i += stride) {
        float4 v = in[i];
        uint32_t h0, l0, h1, l1;
        split2(v.x, v.y, h0, l0);
        split2(v.z, v.w, h1, l1);
        *(uint32_t*)&hi[4*i]     = h0;
        *(uint32_t*)&hi[4*i + 2] = h1;
        *(uint32_t*)&lo[4*i]     = l0;
        *(uint32_t*)&lo[4*i + 2] = l1;
    }
}

// fused RoPE + hi/lo split: reads qkv f32 (does NOT modify it)
// grid (TT, 12), block (32, 4)
__global__ void rope_convert(const float* __restrict__ qkv,
    const float* __restrict__ cosp, const float* __restrict__ sinp,
    __nv_bfloat16* __restrict__ qh, __nv_bfloat16* __restrict__ ql,
    __nv_bfloat16* __restrict__ kh, __nv_bfloat16* __restrict__ kl,
    __nv_bfloat16* __restrict__ vh, __nv_bfloat16* __restrict__ vl)
{
    int t = blockIdx.x;
    int hh = blockIdx.y * 4 + threadIdx.y;
    int d4 = threadIdx.x * 4;
    int srcoff;
    __nv_bfloat16 *dh, *dl;
    size_t dst;
    bool dorope = true;
    if (hh < 32) {
        srcoff = (hh >> 2) * 768 + (hh & 3) * 128;
        dh = qh; dl = ql;
        dst = ((size_t)t * 32 + hh) * 128 + d4;
    } else if (hh < 40) {
        srcoff = (hh - 32) * 768 + 512;
        dh = kh; dl = kl;
        dst = ((size_t)t * 8 + (hh - 32)) * 128 + d4;
    } else {
        srcoff = (hh - 40) * 768 + 640;
        dh = vh; dl = vl;
        dst = ((size_t)t * 8 + (hh - 40)) * 128 + d4;
        dorope = false;
    }
    const float* src = qkv + (size_t)t * QKVO + srcoff;
    float o[4];
    if (dorope) {
        const float* c = cosp + (size_t)t * HDIM;
        const float* s = sinp + (size_t)t * HDIM;
        float4 x  = *(const float4*)(src + d4);
        int p4 = (d4 < 64) ? d4 + 64 : d4 - 64;
        float4 xp = *(const float4*)(src + p4);
        float sg = (d4 < 64) ? -1.f : 1.f;
        o[0] = x.x * c[d4+0] + sg * xp.x * s[d4+0];
        o[1] = x.y * c[d4+1] + sg * xp.y * s[d4+1];
        o[2] = x.z * c[d4+2] + sg * xp.z * s[d4+2];
        o[3] = x.w * c[d4+3] + sg * xp.w * s[d4+3];
    } else {
        float4 x = *(const float4*)(src + d4);
        o[0] = x.x; o[1] = x.y; o[2] = x.z; o[3] = x.w;
    }
    uint32_t h0, l0, h1, l1;
    split2(o[0], o[1], h0, l0);
    split2(o[2], o[3], h1, l1);
    *(uint32_t*)&dh[dst]     = h0;
    *(uint32_t*)&dh[dst + 2] = h1;
    *(uint32_t*)&dl[dst]     = l0;
    *(uint32_t*)&dl[dst + 2] = l1;
}

// =====================================================================
// Pipelined hi/lo GEMM — 2-stage, 2 CTAs/SM, L2 swizzle.
// Epilogues: scatter-atomicAdd / atomicAdd / store / hi-lo split.
// =====================================================================
#define LDKS 40
#define GTS (128 * LDKS)
#define GSTAGE (4 * GTS * 2)
#define GEMM_SMEM (2 * GSTAGE)

__global__ __launch_bounds__(256, 2) void gemm_hl(
    const __nv_bfloat16* __restrict__ Ahi, const __nv_bfloat16* __restrict__ Alo,
    const __nv_bfloat16* __restrict__ Bhi, const __nv_bfloat16* __restrict__ Blo,
    float* __restrict__ C, __nv_bfloat16* __restrict__ Chi, __nv_bfloat16* __restrict__ Clo,
    int M, int N, int K, const int* __restrict__ gatherA,
    const int* __restrict__ scatterC, int addC)
{
    extern __shared__ __nv_bfloat16 smg[];
    uint32_t usm = s2u(smg);

    int tid = threadIdx.x;
    int bm, bn;
    {
        int G = (gridDim.x < 8) ? gridDim.x : 8;
        if (gridDim.x % G) { bn = blockIdx.x; bm = blockIdx.y; }
        else {
            int idb = blockIdx.y * gridDim.x + blockIdx.x;
            int gsz = G * gridDim.y;
            int grp = idb / gsz;
            int rem = idb - grp * gsz;
            bn = grp * G + rem % G;
            bm = rem / G;
        }
    }
    int warp = tid >> 5, lane = tid & 31;
    int wm = warp & 1, wn = warp >> 1;
    int gid = lane >> 2, tig = lane & 3;
    int mi = lane >> 3, lr = lane & 7;

    size_t aoff[2], boff[2];
    uint32_t soffB[2];
#pragma unroll
    for (int i = 0; i < 2; i++) {
        int idx = tid + 256 * i;
        int r = idx >> 2;
        int c8 = (idx & 3) * 8;
        int ar = bm * 128 + r;
        if (gatherA) ar = __ldg(&gatherA[ar]);
        aoff[i] = (size_t)ar * K + c8;
        boff[i] = (size_t)(bn * 128 + r) * K + c8;
        soffB[i] = (uint32_t)(r * LDKS + c8) * 2;
    }

    uint32_t offA = (uint32_t)((wm * 64 + (mi & 1) * 8 + lr) * LDKS + (mi >> 1) * 8) * 2;
    uint32_t offB = (uint32_t)((wn * 32 + (mi >> 1) * 8 + lr) * LDKS + (mi & 1) * 8) * 2;

    float acc[4][4][4];
#pragma unroll
    for (int mt = 0; mt < 4; mt++)
#pragma unroll
        for (int nt = 0; nt < 4; nt++)
#pragma unroll
            for (int e = 0; e < 4; e++) acc[mt][nt][e] = 0.f;

    int nk = K / 32;

#define G_ISSUE(s, k0)                                                     \
    {                                                                      \
        uint32_t sb = usm + (uint32_t)(s) * GSTAGE;                        \
        _Pragma("unroll")                                                  \
        for (int i = 0; i < 2; i++) {                                      \
            cp16(sb + soffB[i],             Ahi + aoff[i] + (k0));         \
            cp16(sb + GTS*2 + soffB[i],     Alo + aoff[i] + (k0));         \
            cp16(sb + 2*GTS*2 + soffB[i],   Bhi + boff[i] + (k0));         \
            cp16(sb + 3*GTS*2 + soffB[i],   Blo + boff[i] + (k0));         \
        }                                                                  \
    }

    G_ISSUE(0, 0); CP_COMMIT();

    for (int t = 0; t < nk; t++) {
        CP_WAIT0();
        __syncthreads();
        if (t + 1 < nk) { G_ISSUE((t + 1) & 1, (t + 1) * 32); CP_COMMIT(); }

        uint32_t sb = usm + (uint32_t)(t & 1) * GSTAGE;
        uint32_t uAh = sb, uAl = sb + GTS * 2;
        uint32_t uBh = sb + 2 * GTS * 2, uBl = sb + 3 * GTS * 2;

#pragma unroll
        for (int kb = 0; kb < 64; kb += 32) {
            uint32_t ah[4][4], al[4][4];
            uint32_t bh[2][4], bl[2][4];
#pragma unroll
            for (int mt = 0; mt < 4; mt++) {
                ldsm4(ah[mt], uAh + offA + mt * (16 * LDKS * 2) + kb);
                ldsm4(al[mt], uAl + offA + mt * (16 * LDKS * 2) + kb);
            }
#pragma unroll
            for (int nn = 0; nn < 2; nn++) {
                ldsm4(bh[nn], uBh + offB + nn * (16 * LDKS * 2) + kb);
                ldsm4(bl[nn], uBl + offB + nn * (16 * LDKS * 2) + kb);
            }
#pragma unroll
            for (int nt = 0; nt < 4; nt++) {
                const uint32_t* bf = bh[nt >> 1] + (nt & 1) * 2;
#pragma unroll
                for (int mt = 0; mt < 4; mt++)
                    mma16816(acc[mt][nt], ah[mt], bf);
            }
#pragma unroll
            for (int nt = 0; nt < 4; nt++) {
                const uint32_t* bf = bl[nt >> 1] + (nt & 1) * 2;
#pragma unroll
                for (int mt = 0; mt < 4; mt++)
                    mma16816(acc[mt][nt], ah[mt], bf);
            }
#pragma unroll
            for (int nt = 0; nt < 4; nt++) {
                const uint32_t* bf = bh[nt >> 1] + (nt & 1) * 2;
#pragma unroll
                for (int mt = 0; mt < 4; mt++)
                    mma16816(acc[mt][nt], al[mt], bf);
            }
        }
    }

    if (scatterC) {
#pragma unroll
        for (int mt = 0; mt < 4; mt++) {
            int r0 = bm * 128 + wm * 64 + mt * 16 + gid;
            int rr0 = __ldg(&scatterC[r0]);
            int rr1 = __ldg(&scatterC[r0 + 8]);
#pragma unroll
            for (int nt = 0; nt < 4; nt++) {
                int c0 = bn * 128 + wn * 32 + nt * 8 + tig * 2;
                atomicAdd(&C[(size_t)rr0 * N + c0],     acc[mt][nt][0]);
                atomicAdd(&C[(size_t)rr0 * N + c0 + 1], acc[mt][nt][1]);
                atomicAdd(&C[(size_t)rr1 * N + c0],     acc[mt][nt][2]);
                atomicAdd(&C[(size_t)rr1 * N + c0 + 1], acc[mt][nt][3]);
            }
        }
    } else if (C) {
        if (addC) {
#pragma unroll
            for (int mt = 0; mt < 4; mt++) {
                int r0 = bm * 128 + wm * 64 + mt * 16 + gid;
#pragma unroll
                for (int nt = 0; nt < 4; nt++) {
                    int c0 = bn * 128 + wn * 32 + nt * 8 + tig * 2;
                    atomicAdd(&C[(size_t)r0 * N + c0],       acc[mt][nt][0]);
                    atomicAdd(&C[(size_t)r0 * N + c0 + 1],   acc[mt][nt][1]);
                    atomicAdd(&C[(size_t)(r0+8) * N + c0],   acc[mt][nt][2]);
                    atomicAdd(&C[(size_t)(r0+8) * N + c0+1], acc[mt][nt][3]);
                }
            }
        } else {
#pragma unroll
            for (int mt = 0; mt < 4; mt++) {
                int r0 = bm * 128 + wm * 64 + mt * 16 + gid;
#pragma unroll
                for (int nt = 0; nt < 4; nt++) {
                    int c0 = bn * 128 + wn * 32 + nt * 8 + tig * 2;
                    *(float2*)&C[(size_t)r0 * N + c0] =
                        make_float2(acc[mt][nt][0], acc[mt][nt][1]);
                    *(float2*)&C[(size_t)(r0 + 8) * N + c0] =
                        make_float2(acc[mt][nt][2], acc[mt][nt][3]);
                }
            }
        }
    } else {
#pragma unroll
        for (int mt = 0; mt < 4; mt++) {
            int r0 = bm * 128 + wm * 64 + mt * 16 + gid;
#pragma unroll
            for (int nt = 0; nt < 4; nt++) {
                int c0 = bn * 128 + wn * 32 + nt * 8 + tig * 2;
                uint32_t h, l;
                split2(acc[mt][nt][0], acc[mt][nt][1], h, l);
                *(uint32_t*)&Chi[(size_t)r0 * N + c0] = h;
                *(uint32_t*)&Clo[(size_t)r0 * N + c0] = l;
                split2(acc[mt][nt][2], acc[mt][nt][3], h, l);
                *(uint32_t*)&Chi[(size_t)(r0 + 8) * N + c0] = h;
                *(uint32_t*)&Clo[(size_t)(r0 + 8) * N + c0] = l;
            }
        }
    }
}

// ---------------- KV-cache fill (reads qkv incl. LoRA) ----------------
__global__ void fill_cache_kernel(const float* __restrict__ qkv,
                                  const int* __restrict__ mem_idx,
                                  const int* __restrict__ blkoff,
                                  const float* __restrict__ bcos,
                                  const float* __restrict__ bsin,
                                  float* __restrict__ kc, float* __restrict__ vc)
{
    int m = blockIdx.x;
    int h = threadIdx.y;
    int d = threadIdx.x;
    int tok = mem_idx[m];
    int blk = blkoff[m >> 6];
    int off = m & 63;
    const float* kb = qkv + (size_t)tok * QKVO + (size_t)(h * 6 + 4) * HDIM;
    const float* vb = qkv + (size_t)tok * QKVO + (size_t)(h * 6 + 5) * HDIM;
    size_t dsti = (((size_t)(blk * 64 + off)) * NKVH + h) * HDIM;
    const float* c = bcos + (size_t)m * HDIM;
    const float* s = bsin + (size_t)m * HDIM;
    float x1 = kb[d], x2 = kb[d + 64];
    kc[dsti + d]      = x1 * c[d]      - x2 * s[d];
    kc[dsti + d + 64] = x2 * c[d + 64] + x1 * s[d + 64];
    vc[dsti + d]      = vb[d];
    vc[dsti + d + 64] = vb[d + 64];
}

// =====================================================================
// Flash attention (mma.sync), causal, GQA 4:1.
// BM=64 (4 warps), KV tile 32, 2 CTAs/SM. Heavy q-blocks first.
// =====================================================================
#define LDH  136
#define FQ64 (64 * LDH)
#define FT32 (32 * LDH)
#define FA3_SMEM ((2 * FQ64 + 2 * 4 * FT32) * 2)

__global__ __launch_bounds__(128, 2) void flash_mma(
    const __nv_bfloat16* __restrict__ qhi, const __nv_bfloat16* __restrict__ qlo,
    const __nv_bfloat16* __restrict__ khi, const __nv_bfloat16* __restrict__ klo,
    const __nv_bfloat16* __restrict__ vhi, const __nv_bfloat16* __restrict__ vlo,
    __nv_bfloat16* __restrict__ ahi_out, __nv_bfloat16* __restrict__ alo_out)
{
    extern __shared__ __nv_bfloat16 smf[];
    uint32_t usm = s2u(smf);
    __nv_bfloat16* Qh = smf;
    __nv_bfloat16* Ql = smf + FQ64;

    int tid = threadIdx.x;
    int wm = tid >> 5, lane = tid & 31;
    int gid = lane >> 2, tig = lane & 3;
    int qb = (gridDim.x - 1) - blockIdx.x;
    int h = blockIdx.y;
    int kvh = h >> 2;

#pragma unroll
    for (int i = 0; i < 8; i++) {
        int idx = tid + 128 * i;
        int r = idx >> 4, c8 = (idx & 15) * 8;
        size_t src = ((size_t)(qb * 64 + r) * 32 + h) * 128 + c8;
        *(uint4*)&Qh[r * LDH + c8] = *(const uint4*)&qhi[src];
        *(uint4*)&Ql[r * LDH + c8] = *(const uint4*)&qlo[src];
    }

    uint32_t kv_goff[4], kv_soff[4];
#pragma unroll
    for (int i = 0; i < 4; i++) {
        int idx = tid + 128 * i;
        int r = idx >> 4, c8 = (idx & 15) * 8;
        kv_goff[i] = (uint32_t)(r * (NKVH * HDIM) + kvh * HDIM + c8);
        kv_soff[i] = (uint32_t)(r * LDH + c8) * 2;
    }

    int nkb = 2 * (qb + 1);

#define F_ISSUE(kb, s)                                                        \
    {                                                                         \
        uint32_t sb = usm + (2 * FQ64 + (s) * 4 * FT32) * 2;                  \
        size_t tb = (size_t)(kb) * 32 * (NKVH * HDIM);                        \
        _Pragma("unroll")                                                     \
        for (int i = 0; i < 4; i++) {                                         \
            cp16(sb + kv_soff[i],            khi + tb + kv_goff[i]);          \
            cp16(sb + FT32*2 + kv_soff[i],   klo + tb + kv_goff[i]);          \
            cp16(sb + 2*FT32*2 + kv_soff[i], vhi + tb + kv_goff[i]);          \
            cp16(sb + 3*FT32*2 + kv_soff[i], vlo + tb + kv_goff[i]);          \
        }                                                                     \
    }

    F_ISSUE(0, 0); CP_COMMIT();

    int mi = lane >> 3, lr = lane & 7;
    uint32_t offQ = (uint32_t)((16 * wm + (mi & 1) * 8 + lr) * LDH + (mi >> 1) * 8) * 2;
    uint32_t offK = (uint32_t)(((mi >> 1) * 8 + lr) * LDH + (mi & 1) * 8) * 2;
    uint32_t offV = (uint32_t)(((mi & 1) * 8 + lr) * LDH + (mi >> 1) * 8) * 2;
    uint32_t uQh = usm, uQl = usm + FQ64 * 2;

    float O[16][4];
#pragma unroll
    for (int nt = 0; nt < 16; nt++)
#pragma unroll
        for (int e = 0; e < 4; e++) O[nt][e] = 0.f;

    float m0 = -1e30f, m1 = -1e30f, l0 = 0.f, l1 = 0.f;
    int qg0 = qb * 64 + wm * 16 + gid;
    int qg1 = qg0 + 8;
    const float scale = 0.08838834764831845f;

    for (int kb = 0; kb < nkb; kb++) {
        CP_WAIT0();
        __syncthreads();
        if (kb + 1 < nkb) { F_ISSUE(kb + 1, (kb + 1) & 1); CP_COMMIT(); }

        uint32_t sb = usm + (2 * FQ64 + (kb & 1) * 4 * FT32) * 2;
        uint32_t uKh = sb, uKl = sb + FT32 * 2;
        uint32_t uVh = sb + 2 * FT32 * 2, uVl = sb + 3 * FT32 * 2;

        float S[4][4];
#pragma unroll
        for (int nt = 0; nt < 4; nt++)
#pragma unroll
            for (int e = 0; e < 4; e++) S[nt][e] = 0.f;

#pragma unroll
        for (int ks = 0; ks < 8; ks++) {
            uint32_t qh4[4], ql4[4];
            ldsm4(qh4, uQh + offQ + ks * 32);
            ldsm4(ql4, uQl + offQ + ks * 32);
#pragma unroll
            for (int ntp = 0; ntp < 2; ntp++) {
                uint32_t kh4[4], kl4[4];
                ldsm4(kh4, uKh + offK + ntp * (16 * LDH * 2) + ks * 32);
                ldsm4(kl4, uKl + offK + ntp * (16 * LDH * 2) + ks * 32);
                mma16816(S[2 * ntp],     qh4, kh4);
                mma16816(S[2 * ntp + 1], qh4, kh4 + 2);
                mma16816(S[2 * ntp],     qh4, kl4);
                mma16816(S[2 * ntp + 1], qh4, kl4 + 2);
                mma16816(S[2 * ntp],     ql4, kh4);
                mma16816(S[2 * ntp + 1], ql4, kh4 + 2);
            }
        }

        int kvb = kb * 32;
        float rmax0 = -1e30f, rmax1 = -1e30f;
#pragma unroll
        for (int nt = 0; nt < 4; nt++) {
            int kg = kvb + nt * 8 + tig * 2;
            float s0 = (kg     <= qg0) ? S[nt][0] * scale : -1e30f;
            float s1 = (kg + 1 <= qg0) ? S[nt][1] * scale : -1e30f;
            float s2 = (kg     <= qg1) ? S[nt][2] * scale : -1e30f;
            float s3 = (kg + 1 <= qg1) ? S[nt][3] * scale : -1e30f;
            S[nt][0] = s0; S[nt][1] = s1; S[nt][2] = s2; S[nt][3] = s3;
            rmax0 = fmaxf(rmax0, fmaxf(s0, s1));
            rmax1 = fmaxf(rmax1, fmaxf(s2, s3));
        }
        rmax0 = fmaxf(rmax0, __shfl_xor_sync(0xffffffffu, rmax0, 1));
        rmax0 = fmaxf(rmax0, __shfl_xor_sync(0xffffffffu, rmax0, 2));
        rmax1 = fmaxf(rmax1, __shfl_xor_sync(0xffffffffu, rmax1, 1));
        rmax1 = fmaxf(rmax1, __shfl_xor_sync(0xffffffffu, rmax1, 2));

        float mn0 = fmaxf(m0, rmax0), mn1 = fmaxf(m1, rmax1);
        float f0 = __expf(m0 - mn0), f1 = __expf(m1 - mn1);
        m0 = mn0; m1 = mn1;

        float ls0 = 0.f, ls1 = 0.f;
#pragma unroll
        for (int nt = 0; nt < 4; nt++) {
            float p0 = __expf(S[nt][0] - mn0);
            float p1 = __expf(S[nt][1] - mn0);
            float p2 = __expf(S[nt][2] - mn1);
            float p3 = __expf(S[nt][3] - mn1);
            S[nt][0] = p0; S[nt][1] = p1; S[nt][2] = p2; S[nt][3] = p3;
            ls0 += p0 + p1; ls1 += p2 + p3;
        }
        ls0 += __shfl_xor_sync(0xffffffffu, ls0, 1);
        ls0 += __shfl_xor_sync(0xffffffffu, ls0, 2);
        ls1 += __shfl_xor_sync(0xffffffffu, ls1, 1);
        ls1 += __shfl_xor_sync(0xffffffffu, ls1, 2);
        l0 = l0 * f0 + ls0;
        l1 = l1 * f1 + ls1;

#pragma unroll
        for (int nt = 0; nt < 16; nt++) {
            O[nt][0] *= f0; O[nt][1] *= f0;
            O[nt][2] *= f1; O[nt][3] *= f1;
        }

#pragma unroll
        for (int ks2 = 0; ks2 < 2; ks2++) {
            uint32_t ahi[4], alo[4];
            split2(S[2 * ks2][0],     S[2 * ks2][1],     ahi[0], alo[0]);
            split2(S[2 * ks2][2],     S[2 * ks2][3],     ahi[1], alo[1]);
            split2(S[2 * ks2 + 1][0], S[2 * ks2 + 1][1], ahi[2], alo[2]);
            split2(S[2 * ks2 + 1][2], S[2 * ks2 + 1][3], ahi[3], alo[3]);
#pragma unroll
            for (int ntp = 0; ntp < 8; ntp++) {
                uint32_t vh4[4], vl4[4];
                ldsm4t(vh4, uVh + offV + ks2 * (16 * LDH * 2) + ntp * 32);
                ldsm4t(vl4, uVl + offV + ks2 * (16 * LDH * 2) + ntp * 32);
                mma16816(O[2 * ntp],     ahi, vh4);
                mma16816(O[2 * ntp + 1], ahi, vh4 + 2);
                mma16816(O[2 * ntp],     ahi, vl4);
                mma16816(O[2 * ntp + 1], ahi, vl4 + 2);
                mma16816(O[2 * ntp],     alo, vh4);
                mma16816(O[2 * ntp + 1], alo, vh4 + 2);
            }
        }
    }

    float inv0 = 1.f / l0, inv1 = 1.f / l1;
    size_t ob0 = (size_t)(qb * 64 + wm * 16 + gid) * HID + (size_t)h * HDIM;
    size_t ob1 = ob0 + 8 * (size_t)HID;
#pragma unroll
    for (int nt = 0; nt < 16; nt++) {
        int col = nt * 8 + tig * 2;
        uint32_t hh, ll;
        split2(O[nt][0] * inv0, O[nt][1] * inv0, hh, ll);
        *(uint32_t*)&ahi_out[ob0 + col] = hh;
        *(uint32_t*)&alo_out[ob0 + col] = ll;
        split2(O[nt][2] * inv1, O[nt][3] * inv1, hh, ll);
        *(uint32_t*)&ahi_out[ob1 + col] = hh;
        *(uint32_t*)&alo_out[ob1 + col] = ll;
    }
}

// =====================================================================
// Host orchestration — multi-stream fork/join (graph-capturable)
// =====================================================================
static void convS(cudaStream_t st, const void* in, __nv_bfloat16* hi,
                  __nv_bfloat16* lo, size_t n) {
    int n4 = (int)(n / 4);
    int blocks = (n4 + 255) / 256;
    if (blocks > 6144) blocks = 6144;
    conv_split<<<blocks, 256, 0, st>>>((const float4*)in, hi, lo, n4);
}

#define SYM(v, s) cudaGetSymbolAddress((void**)&v, s)

extern "C" void kernel_launch(void* const* d_in, const int* in_sizes, int n_in,
                              void* d_out, int out_size)
{
    const float* hs     = (const float*)d_in[0];
    const float* cosp   = (const float*)d_in[1];
    const float* sinp   = (const float*)d_in[2];
    const float* bcos   = (const float*)d_in[3];
    const float* bsin   = (const float*)d_in[4];
    const int*   memidx = (const int*)d_in[5];
    const int*   imidx  = (const int*)d_in[6];
    const float* kc_in  = (const float*)d_in[7];
    const float* vc_in  = (const float*)d_in[8];
    const int*   blkoff = (const int*)d_in[9];
    const float* wqkv_w = (const float*)d_in[10];
    const float* wqkv_A = (const float*)d_in[11];
    const float* wqkv_B = (const float*)d_in[12];
    const float* wqkv_MA= (const float*)d_in[13];
    const float* wqkv_MB= (const float*)d_in[14];
    const float* wo_w   = (const float*)d_in[15];
    const float* wo_A   = (const float*)d_in[16];
    const float* wo_B   = (const float*)d_in[17];
    const float* wo_MA  = (const float*)d_in[18];
    const float* wo_MB  = (const float*)d_in[19];

    float* outp   = (float*)d_out;
    float* kc_out = outp + (size_t)TT * HID;
    float* vc_out = kc_out + CACHE_ELEMS;

    float *qkv;
    SYM(qkv, g_qkv);

    __nv_bfloat16 *hs_hi,*hs_lo,*attn_hi,*attn_lo,*q_hi,*q_lo,*k_hi,*k_lo,*v_hi,*v_lo;
    __nv_bfloat16 *tim_hi,*tim_lo,*tmem_hi,*tmem_lo;
    __nv_bfloat16 *wqkv_hi,*wqkv_lo,*wqA_hi,*wqA_lo,*wqB_hi,*wqB_lo,*wqMA_hi,*wqMA_lo,*wqMB_hi,*wqMB_lo;
    __nv_bfloat16 *wo_hi,*wo_lo,*woA_hi,*woA_lo,*woB_hi,*woB_lo,*woMA_hi,*woMA_lo,*woMB_hi,*woMB_lo;
    SYM(hs_hi, g_hs_hi);     SYM(hs_lo, g_hs_lo);
    SYM(attn_hi, g_attn_hi); SYM(attn_lo, g_attn_lo);
    SYM(q_hi, g_q_hi);       SYM(q_lo, g_q_lo);
    SYM(k_hi, g_k_hi);       SYM(k_lo, g_k_lo);
    SYM(v_hi, g_v_hi);       SYM(v_lo, g_v_lo);
    SYM(tim_hi, g_tim_hi);   SYM(tim_lo, g_tim_lo);
    SYM(tmem_hi, g_tmem_hi); SYM(tmem_lo, g_tmem_lo);
    SYM(wqkv_hi, g_wqkv_hi); SYM(wqkv_lo, g_wqkv_lo);
    SYM(wqA_hi, g_wqA_hi);   SYM(wqA_lo, g_wqA_lo);
    SYM(wqB_hi, g_wqB_hi);   SYM(wqB_lo, g_wqB_lo);
    SYM(wqMA_hi, g_wqMA_hi); SYM(wqMA_lo, g_wqMA_lo);
    SYM(wqMB_hi, g_wqMB_hi); SYM(wqMB_lo, g_wqMB_lo);
    SYM(wo_hi, g_wo_hi);     SYM(wo_lo, g_wo_lo);
    SYM(woA_hi, g_woA_hi);   SYM(woA_lo, g_woA_lo);
    SYM(woB_hi, g_woB_hi);   SYM(woB_lo, g_woB_lo);
    SYM(woMA_hi, g_woMA_hi); SYM(woMA_lo, g_woMA_lo);
    SYM(woMB_hi, g_woMB_hi); SYM(woMB_lo, g_woMB_lo);

    cudaFuncSetAttribute(gemm_hl, cudaFuncAttributeMaxDynamicSharedMemorySize, GEMM_SMEM);
    cudaFuncSetAttribute(flash_mma, cudaFuncAttributeMaxDynamicSharedMemorySize, FA3_SMEM);

    cudaStream_t s1, s2;
    cudaStreamCreateWithFlags(&s1, cudaStreamNonBlocking);
    cudaStreamCreateWithFlags(&s2, cudaStreamNonBlocking);
    cudaEvent_t eFork, eHs, eWqA, eWqB, eQKV, eCpy, eWoC, eQall, eFlash, eLraB, eWoA, eS1, eS2, eZq;
    cudaEvent_t* evs[14] = {&eFork,&eHs,&eWqA,&eWqB,&eQKV,&eCpy,&eWoC,&eQall,&eFlash,&eLraB,&eWoA,&eS1,&eS2,&eZq};
    for (int i = 0; i < 14; i++) cudaEventCreateWithFlags(evs[i], cudaEventDisableTiming);

    // ---- fork immediately ----
    cudaEventRecord(eFork, 0);
    cudaStreamWaitEvent(s1, eFork, 0);
    cudaStreamWaitEvent(s2, eFork, 0);

    // s2: zero qkv (QKV main + LoRA-B will both atomicAdd into it)
    cudaMemsetAsync(qkv, 0, (size_t)TT * QKVO * sizeof(float), s2);
    cudaEventRecord(eZq, s2);

    // s1: zero out region, hs + LoRA-A/B weight conversions
    cudaMemsetAsync(outp, 0, (size_t)TT * HID * sizeof(float), s1);
    convS(s1, hs, hs_hi, hs_lo, (size_t)TT * HID);
    cudaEventRecord(eHs, s1);
    convS(s1, wqkv_A, wqA_hi, wqA_lo, (size_t)RANK * HID);
    convS(s1, wqkv_MA, wqMA_hi, wqMA_lo, (size_t)RANK * HID);
    cudaEventRecord(eWqA, s1);
    convS(s1, wqkv_B, wqB_hi, wqB_lo, (size_t)QKVO * RANK);
    convS(s1, wqkv_MB, wqMB_hi, wqMB_lo, (size_t)QKVO * RANK);
    cudaEventRecord(eWqB, s1);

    // origin: big weight conversion then QKV main projection (atomicAdd)
    convS(0, wqkv_w, wqkv_hi, wqkv_lo, (size_t)QKVO * HID);
    cudaStreamWaitEvent(0, eHs, 0);
    cudaStreamWaitEvent(0, eZq, 0);
    gemm_hl<<<dim3(QKVO/128, TT/128), 256, GEMM_SMEM>>>(hs_hi, hs_lo, wqkv_hi, wqkv_lo,
        qkv, nullptr, nullptr, TT, QKVO, HID, nullptr, nullptr, 1);
    cudaEventRecord(eQKV, 0);

    // s1: cache memcpys + WO-side conversions
    cudaMemcpyAsync(kc_out, kc_in, (size_t)CACHE_ELEMS * sizeof(float),
                    cudaMemcpyDeviceToDevice, s1);
    cudaMemcpyAsync(vc_out, vc_in, (size_t)CACHE_ELEMS * sizeof(float),
                    cudaMemcpyDeviceToDevice, s1);
    cudaEventRecord(eCpy, s1);
    convS(s1, wo_w, wo_hi, wo_lo, (size_t)HID * HID);
    convS(s1, wo_A, woA_hi, woA_lo, (size_t)RANK * HID);
    convS(s1, wo_MA, woMA_hi, woMA_lo, (size_t)RANK * HID);
    convS(s1, wo_B, woB_hi, woB_lo, (size_t)HID * RANK);
    convS(s1, wo_MB, woMB_hi, woMB_lo, (size_t)HID * RANK);
    cudaEventRecord(eWoC, s1);
    cudaEventRecord(eS1, s1);

    // ---- s2: QKV LoRA (A then B); B overlaps QKV main's tail ----
    cudaStreamWaitEvent(s2, eWqA, 0);
    gemm_hl<<<dim3(RANK/128, NIM/128), 256, GEMM_SMEM, s2>>>(hs_hi, hs_lo, wqA_hi, wqA_lo,
        nullptr, tim_hi, tim_lo, NIM, RANK, HID, imidx, nullptr, 0);
    gemm_hl<<<dim3(RANK/128, NMEM/128), 256, GEMM_SMEM, s2>>>(hs_hi, hs_lo, wqMA_hi, wqMA_lo,
        nullptr, tmem_hi, tmem_lo, NMEM, RANK, HID, memidx, nullptr, 0);
    cudaStreamWaitEvent(s2, eWqB, 0);
    gemm_hl<<<dim3(QKVO/128, NIM/128), 256, GEMM_SMEM, s2>>>(tim_hi, tim_lo, wqB_hi, wqB_lo,
        qkv, nullptr, nullptr, NIM, QKVO, RANK, nullptr, imidx, 0);
    gemm_hl<<<dim3(QKVO/128, NMEM/128), 256, GEMM_SMEM, s2>>>(tmem_hi, tmem_lo, wqMB_hi, wqMB_lo,
        qkv, nullptr, nullptr, NMEM, QKVO, RANK, nullptr, memidx, 0);
    // cache fill + rope need FULL qkv (main + LoRA): wait eQKV too
    cudaStreamWaitEvent(s2, eQKV, 0);
    cudaStreamWaitEvent(s2, eCpy, 0);
    fill_cache_kernel<<<NMEM, dim3(64, 8), 0, s2>>>(qkv, memidx, blkoff, bcos, bsin, kc_out, vc_out);
    rope_convert<<<dim3(TT, 12), dim3(32, 4), 0, s2>>>(qkv, cosp, sinp, q_hi, q_lo, k_hi, k_lo, v_hi, v_lo);
    cudaEventRecord(eQall, s2);

    // ---- origin: flash attention (single launch, heavy-first) ----
    cudaStreamWaitEvent(0, eQall, 0);
    flash_mma<<<dim3(TT/64, NHEADS), 128, FA3_SMEM>>>(q_hi, q_lo, k_hi, k_lo,
        v_hi, v_lo, attn_hi, attn_lo);
    cudaEventRecord(eFlash, 0);

    // ---- s2: WO LoRA-A then LoRA-B (B overlaps WO main) ----
    cudaStreamWaitEvent(s2, eFlash, 0);
    cudaStreamWaitEvent(s2, eWoC, 0);
    gemm_hl<<<dim3(RANK/128, NIM/128), 256, GEMM_SMEM, s2>>>(attn_hi, attn_lo, woA_hi, woA_lo,
        nullptr, tim_hi, tim_lo, NIM, RANK, HID, imidx, nullptr, 0);
    gemm_hl<<<dim3(RANK/128, NMEM/128), 256, GEMM_SMEM, s2>>>(attn_hi, attn_lo, woMA_hi, woMA_lo,
        nullptr, tmem_hi, tmem_lo, NMEM, RANK, HID, memidx, nullptr, 0);
    gemm_hl<<<dim3(HID/128, NIM/128), 256, GEMM_SMEM, s2>>>(tim_hi, tim_lo, woB_hi, woB_lo,
        outp, nullptr, nullptr, NIM, HID, RANK, nullptr, imidx, 0);
    gemm_hl<<<dim3(HID/128, NMEM/128), 256, GEMM_SMEM, s2>>>(tmem_hi, tmem_lo, woMB_hi, woMB_lo,
        outp, nullptr, nullptr, NMEM, HID, RANK, nullptr, memidx, 0);
    cudaEventRecord(eS2, s2);

    // ---- origin: WO main projection (atomicAdd into zeroed out) ----
    cudaStreamWaitEvent(0, eWoC, 0);
    gemm_hl<<<dim3(HID/128, TT/128), 256, GEMM_SMEM>>>(attn_hi, attn_lo, wo_hi, wo_lo,
        outp, nullptr, nullptr, TT, HID, HID, nullptr, nullptr, 1);

    // ---- join forked streams back into origin ----
    cudaStreamWaitEvent(0, eS1, 0);
    cudaStreamWaitEvent(0, eS2, 0);

    cudaStreamCaptureStatus st = cudaStreamCaptureStatusNone;
    cudaStreamIsCapturing(0, &st);
    if (st == cudaStreamCaptureStatusNone) {
        for (int i = 0; i < 14; i++) cudaEventDestroy(*evs[i]);
        cudaStreamDestroy(s1);
        cudaStreamDestroy(s2);
    }
}

// round 15
// speedup vs baseline: 1.0995x; 1.0995x over previous
#include <cuda_runtime.h>
#include <cuda_bf16.h>
#include <math.h>
#include <float.h>
#include <stdint.h>

#define TT     2048
#define HID    4096
#define NHEADS 32
#define NKVH   8
#define HDIM   128
#define QKVO   6144
#define RANK   256
#define NIM    512
#define NMEM   128
#define CACHE_ELEMS (4*64*NKVH*HDIM)

// ---------------- scratch ----------------
__device__ float g_qkv[TT * QKVO];

__device__ __nv_bfloat16 g_hs_hi[TT*HID],    g_hs_lo[TT*HID];
__device__ __nv_bfloat16 g_attn_hi[TT*HID],  g_attn_lo[TT*HID];
__device__ __nv_bfloat16 g_q_hi[TT*HID],     g_q_lo[TT*HID];
__device__ __nv_bfloat16 g_k_hi[TT*NKVH*HDIM], g_k_lo[TT*NKVH*HDIM];
__device__ __nv_bfloat16 g_v_hi[TT*NKVH*HDIM], g_v_lo[TT*NKVH*HDIM];
__device__ __nv_bfloat16 g_tim_hi[NIM*RANK],  g_tim_lo[NIM*RANK];
__device__ __nv_bfloat16 g_tmem_hi[NMEM*RANK], g_tmem_lo[NMEM*RANK];

__device__ __nv_bfloat16 g_wqkv_hi[QKVO*HID], g_wqkv_lo[QKVO*HID];
__device__ __nv_bfloat16 g_wqA_hi[RANK*HID],  g_wqA_lo[RANK*HID];
__device__ __nv_bfloat16 g_wqB_hi[QKVO*RANK], g_wqB_lo[QKVO*RANK];
__device__ __nv_bfloat16 g_wqMA_hi[RANK*HID], g_wqMA_lo[RANK*HID];
__device__ __nv_bfloat16 g_wqMB_hi[QKVO*RANK],g_wqMB_lo[QKVO*RANK];
__device__ __nv_bfloat16 g_wo_hi[HID*HID],    g_wo_lo[HID*HID];
__device__ __nv_bfloat16 g_woA_hi[RANK*HID],  g_woA_lo[RANK*HID];
__device__ __nv_bfloat16 g_woB_hi[HID*RANK],  g_woB_lo[HID*RANK];
__device__ __nv_bfloat16 g_woMA_hi[RANK*HID], g_woMA_lo[RANK*HID];
__device__ __nv_bfloat16 g_woMB_hi[HID*RANK], g_woMB_lo[HID*RANK];

// ---------------- helpers ----------------
__device__ __forceinline__ uint32_t pack_bf16(float x, float y) {
    __nv_bfloat162 t = __floats2bfloat162_rn(x, y);
    return *reinterpret_cast<uint32_t*>(&t);
}
__device__ __forceinline__ void split2(float x, float y, uint32_t& h, uint32_t& l) {
    float hx = __bfloat162float(__float2bfloat16(x));
    float hy = __bfloat162float(__float2bfloat16(y));
    h = pack_bf16(x, y);
    l = pack_bf16(x - hx, y - hy);
}
__device__ __forceinline__ void mma16816(float* c, const uint32_t* a, const uint32_t* b) {
    asm volatile(
        "mma.sync.aligned.m16n8k16.row.col.f32.bf16.bf16.f32 "
        "{%0,%1,%2,%3}, {%4,%5,%6,%7}, {%8,%9}, {%0,%1,%2,%3};\n"
        : "+f"(c[0]), "+f"(c[1]), "+f"(c[2]), "+f"(c[3])
        : "r"(a[0]), "r"(a[1]), "r"(a[2]), "r"(a[3]), "r"(b[0]), "r"(b[1]));
}
__device__ __forceinline__ uint32_t s2u(const void* p) {
    return (uint32_t)__cvta_generic_to_shared(p);
}
__device__ __forceinline__ void cp16(uint32_t saddr, const void* gaddr) {
    asm volatile("cp.async.cg.shared.global [%0], [%1], 16;\n" :: "r"(saddr), "l"(gaddr));
}
#define CP_COMMIT() asm volatile("cp.async.commit_group;\n")
#define CP_WAIT0()  asm volatile("cp.async.wait_group 0;\n")
__device__ __forceinline__ void ldsm4(uint32_t* r, uint32_t saddr) {
    asm volatile("ldmatrix.sync.aligned.m8n8.x4.shared.b16 {%0,%1,%2,%3}, [%4];\n"
        : "=r"(r[0]), "=r"(r[1]), "=r"(r[2]), "=r"(r[3]) : "r"(saddr));
}
__device__ __forceinline__ void ldsm4t(uint32_t* r, uint32_t saddr) {
    asm volatile("ldmatrix.sync.aligned.m8n8.x4.trans.shared.b16 {%0,%1,%2,%3}, [%4];\n"
        : "=r"(r[0]), "=r"(r[1]), "=r"(r[2]), "=r"(r[3]) : "r"(saddr));
}

// ---------------- split conversion ----------------
__global__ void conv_split(const float4* __restrict__ in,
                           __nv_bfloat16* __restrict__ hi,
                           __nv_bfloat16* __restrict__ lo, int n4)
{
    int i = blockIdx.x * blockDim.x + threadIdx.x;
    int stride = gridDim.x * blockDim.x;
    for (; i < n4; i += stride) {
        float4 v = in[i];
        uint32_t h0, l0, h1, l1;
        split2(v.x, v.y, h0, l0);
        split2(v.z, v.w, h1, l1);
        *(uint32_t*)&hi[4*i]     = h0;
        *(uint32_t*)&hi[4*i + 2] = h1;
        *(uint32_t*)&lo[4*i]     = l0;
        *(uint32_t*)&lo[4*i + 2] = l1;
    }
}

// fused RoPE + hi/lo split: reads RAW qkv f32 (does NOT modify it)
// grid (TT, 12), block (32, 4)
__global__ void rope_convert(const float* __restrict__ qkv,
    const float* __restrict__ cosp, const float* __restrict__ sinp,
    __nv_bfloat16* __restrict__ qh, __nv_bfloat16* __restrict__ ql,
    __nv_bfloat16* __restrict__ kh, __nv_bfloat16* __restrict__ kl,
    __nv_bfloat16* __restrict__ vh, __nv_bfloat16* __restrict__ vl)
{
    int t = blockIdx.x;
    int hh = blockIdx.y * 4 + threadIdx.y;
    int d4 = threadIdx.x * 4;
    int srcoff;
    __nv_bfloat16 *dh, *dl;
    size_t dst;
    bool dorope = true;
    if (hh < 32) {
        srcoff = (hh >> 2) * 768 + (hh & 3) * 128;
        dh = qh; dl = ql;
        dst = ((size_t)t * 32 + hh) * 128 + d4;
    } else if (hh < 40) {
        srcoff = (hh - 32) * 768 + 512;
        dh = kh; dl = kl;
        dst = ((size_t)t * 8 + (hh - 32)) * 128 + d4;
    } else {
        srcoff = (hh - 40) * 768 + 640;
        dh = vh; dl = vl;
        dst = ((size_t)t * 8 + (hh - 40)) * 128 + d4;
        dorope = false;
    }
    const float* src = qkv + (size_t)t * QKVO + srcoff;
    float o[4];
    if (dorope) {
        const float* c = cosp + (size_t)t * HDIM;
        const float* s = sinp + (size_t)t * HDIM;
        float4 x  = *(const float4*)(src + d4);
        int p4 = (d4 < 64) ? d4 + 64 : d4 - 64;
        float4 xp = *(const float4*)(src + p4);
        float sg = (d4 < 64) ? -1.f : 1.f;
        o[0] = x.x * c[d4+0] + sg * xp.x * s[d4+0];
        o[1] = x.y * c[d4+1] + sg * xp.y * s[d4+1];
        o[2] = x.z * c[d4+2] + sg * xp.z * s[d4+2];
        o[3] = x.w * c[d4+3] + sg * xp.w * s[d4+3];
    } else {
        float4 x = *(const float4*)(src + d4);
        o[0] = x.x; o[1] = x.y; o[2] = x.z; o[3] = x.w;
    }
    uint32_t h0, l0, h1, l1;
    split2(o[0], o[1], h0, l0);
    split2(o[2], o[3], h1, l1);
    *(uint32_t*)&dh[dst]     = h0;
    *(uint32_t*)&dh[dst + 2] = h1;
    *(uint32_t*)&dl[dst]     = l0;
    *(uint32_t*)&dl[dst + 2] = l1;
}

// =====================================================================
// Pipelined hi/lo GEMM — 2-stage, 2 CTAs/SM, L2 swizzle
// =====================================================================
#define LDKS 40
#define GTS (128 * LDKS)
#define GSTAGE (4 * GTS * 2)
#define GEMM_SMEM (2 * GSTAGE)

__global__ __launch_bounds__(256, 2) void gemm_hl(
    const __nv_bfloat16* __restrict__ Ahi, const __nv_bfloat16* __restrict__ Alo,
    const __nv_bfloat16* __restrict__ Bhi, const __nv_bfloat16* __restrict__ Blo,
    float* __restrict__ C, __nv_bfloat16* __restrict__ Chi, __nv_bfloat16* __restrict__ Clo,
    int M, int N, int K, const int* __restrict__ gatherA,
    const int* __restrict__ scatterC)
{
    extern __shared__ __nv_bfloat16 smg[];
    uint32_t usm = s2u(smg);

    int tid = threadIdx.x;
    int bm, bn;
    {
        int G = (gridDim.x < 8) ? gridDim.x : 8;
        if (gridDim.x % G) { bn = blockIdx.x; bm = blockIdx.y; }
        else {
            int idb = blockIdx.y * gridDim.x + blockIdx.x;
            int gsz = G * gridDim.y;
            int grp = idb / gsz;
            int rem = idb - grp * gsz;
            bn = grp * G + rem % G;
            bm = rem / G;
        }
    }
    int warp = tid >> 5, lane = tid & 31;
    int wm = warp & 1, wn = warp >> 1;
    int gid = lane >> 2, tig = lane & 3;
    int mi = lane >> 3, lr = lane & 7;

    size_t aoff[2], boff[2];
    uint32_t soffB[2];
#pragma unroll
    for (int i = 0; i < 2; i++) {
        int idx = tid + 256 * i;
        int r = idx >> 2;
        int c8 = (idx & 3) * 8;
        int ar = bm * 128 + r;
        if (gatherA) ar = __ldg(&gatherA[ar]);
        aoff[i] = (size_t)ar * K + c8;
        boff[i] = (size_t)(bn * 128 + r) * K + c8;
        soffB[i] = (uint32_t)(r * LDKS + c8) * 2;
    }

    uint32_t offA = (uint32_t)((wm * 64 + (mi & 1) * 8 + lr) * LDKS + (mi >> 1) * 8) * 2;
    uint32_t offB = (uint32_t)((wn * 32 + (mi >> 1) * 8 + lr) * LDKS + (mi & 1) * 8) * 2;

    float acc[4][4][4];
#pragma unroll
    for (int mt = 0; mt < 4; mt++)
#pragma unroll
        for (int nt = 0; nt < 4; nt++)
#pragma unroll
            for (int e = 0; e < 4; e++) acc[mt][nt][e] = 0.f;

    int nk = K / 32;

#define G_ISSUE(s, k0)                                                     \
    {                                                                      \
        uint32_t sb = usm + (uint32_t)(s) * GSTAGE;                        \
        _Pragma("unroll")                                                  \
        for (int i = 0; i < 2; i++) {                                      \
            cp16(sb + soffB[i],             Ahi + aoff[i] + (k0));         \
            cp16(sb + GTS*2 + soffB[i],     Alo + aoff[i] + (k0));         \
            cp16(sb + 2*GTS*2 + soffB[i],   Bhi + boff[i] + (k0));         \
            cp16(sb + 3*GTS*2 + soffB[i],   Blo + boff[i] + (k0));         \
        }                                                                  \
    }

    G_ISSUE(0, 0); CP_COMMIT();

    for (int t = 0; t < nk; t++) {
        CP_WAIT0();
        __syncthreads();
        if (t + 1 < nk) { G_ISSUE((t + 1) & 1, (t + 1) * 32); CP_COMMIT(); }

        uint32_t sb = usm + (uint32_t)(t & 1) * GSTAGE;
        uint32_t uAh = sb, uAl = sb + GTS * 2;
        uint32_t uBh = sb + 2 * GTS * 2, uBl = sb + 3 * GTS * 2;

#pragma unroll
        for (int kb = 0; kb < 64; kb += 32) {
            uint32_t ah[4][4], al[4][4];
            uint32_t bh[2][4], bl[2][4];
#pragma unroll
            for (int mt = 0; mt < 4; mt++) {
                ldsm4(ah[mt], uAh + offA + mt * (16 * LDKS * 2) + kb);
                ldsm4(al[mt], uAl + offA + mt * (16 * LDKS * 2) + kb);
            }
#pragma unroll
            for (int nn = 0; nn < 2; nn++) {
                ldsm4(bh[nn], uBh + offB + nn * (16 * LDKS * 2) + kb);
                ldsm4(bl[nn], uBl + offB + nn * (16 * LDKS * 2) + kb);
            }
#pragma unroll
            for (int nt = 0; nt < 4; nt++) {
                const uint32_t* bf = bh[nt >> 1] + (nt & 1) * 2;
#pragma unroll
                for (int mt = 0; mt < 4; mt++)
                    mma16816(acc[mt][nt], ah[mt], bf);
            }
#pragma unroll
            for (int nt = 0; nt < 4; nt++) {
                const uint32_t* bf = bl[nt >> 1] + (nt & 1) * 2;
#pragma unroll
                for (int mt = 0; mt < 4; mt++)
                    mma16816(acc[mt][nt], ah[mt], bf);
            }
#pragma unroll
            for (int nt = 0; nt < 4; nt++) {
                const uint32_t* bf = bh[nt >> 1] + (nt & 1) * 2;
#pragma unroll
                for (int mt = 0; mt < 4; mt++)
                    mma16816(acc[mt][nt], al[mt], bf);
            }
        }
    }

    if (scatterC) {
#pragma unroll
        for (int mt = 0; mt < 4; mt++) {
            int r0 = bm * 128 + wm * 64 + mt * 16 + gid;
            int rr0 = __ldg(&scatterC[r0]);
            int rr1 = __ldg(&scatterC[r0 + 8]);
#pragma unroll
            for (int nt = 0; nt < 4; nt++) {
                int c0 = bn * 128 + wn * 32 + nt * 8 + tig * 2;
                atomicAdd(&C[(size_t)rr0 * N + c0],     acc[mt][nt][0]);
                atomicAdd(&C[(size_t)rr0 * N + c0 + 1], acc[mt][nt][1]);
                atomicAdd(&C[(size_t)rr1 * N + c0],     acc[mt][nt][2]);
                atomicAdd(&C[(size_t)rr1 * N + c0 + 1], acc[mt][nt][3]);
            }
        }
    } else if (C) {
#pragma unroll
        for (int mt = 0; mt < 4; mt++) {
            int r0 = bm * 128 + wm * 64 + mt * 16 + gid;
#pragma unroll
            for (int nt = 0; nt < 4; nt++) {
                int c0 = bn * 128 + wn * 32 + nt * 8 + tig * 2;
                *(float2*)&C[(size_t)r0 * N + c0] =
                    make_float2(acc[mt][nt][0], acc[mt][nt][1]);
                *(float2*)&C[(size_t)(r0 + 8) * N + c0] =
                    make_float2(acc[mt][nt][2], acc[mt][nt][3]);
            }
        }
    } else {
#pragma unroll
        for (int mt = 0; mt < 4; mt++) {
            int r0 = bm * 128 + wm * 64 + mt * 16 + gid;
#pragma unroll
            for (int nt = 0; nt < 4; nt++) {
                int c0 = bn * 128 + wn * 32 + nt * 8 + tig * 2;
                uint32_t h, l;
                split2(acc[mt][nt][0], acc[mt][nt][1], h, l);
                *(uint32_t*)&Chi[(size_t)r0 * N + c0] = h;
                *(uint32_t*)&Clo[(size_t)r0 * N + c0] = l;
                split2(acc[mt][nt][2], acc[mt][nt][3], h, l);
                *(uint32_t*)&Chi[(size_t)(r0 + 8) * N + c0] = h;
                *(uint32_t*)&Clo[(size_t)(r0 + 8) * N + c0] = l;
            }
        }
    }
}

// ---------------- KV-cache fill (reads qkv incl. LoRA) ----------------
__global__ void fill_cache_kernel(const float* __restrict__ qkv,
                                  const int* __restrict__ mem_idx,
                                  const int* __restrict__ blkoff,
                                  const float* __restrict__ bcos,
                                  const float* __restrict__ bsin,
                                  float* __restrict__ kc, float* __restrict__ vc)
{
    int m = blockIdx.x;
    int h = threadIdx.y;
    int d = threadIdx.x;
    int tok = mem_idx[m];
    int blk = blkoff[m >> 6];
    int off = m & 63;
    const float* kb = qkv + (size_t)tok * QKVO + (size_t)(h * 6 + 4) * HDIM;
    const float* vb = qkv + (size_t)tok * QKVO + (size_t)(h * 6 + 5) * HDIM;
    size_t dsti = (((size_t)(blk * 64 + off)) * NKVH + h) * HDIM;
    const float* c = bcos + (size_t)m * HDIM;
    const float* s = bsin + (size_t)m * HDIM;
    float x1 = kb[d], x2 = kb[d + 64];
    kc[dsti + d]      = x1 * c[d]      - x2 * s[d];
    kc[dsti + d + 64] = x2 * c[d + 64] + x1 * s[d + 64];
    vc[dsti + d]      = vb[d];
    vc[dsti + d + 64] = vb[d + 64];
}

// =====================================================================
// Flash attention (mma.sync), causal, GQA 4:1.
// BM=64 (4 warps), KV tile 32, 2 CTAs/SM. Heavy q-blocks first.
// =====================================================================
#define LDH  136
#define FQ64 (64 * LDH)
#define FT32 (32 * LDH)
#define FA3_SMEM ((2 * FQ64 + 2 * 4 * FT32) * 2)

__global__ __launch_bounds__(128, 2) void flash_mma(
    const __nv_bfloat16* __restrict__ qhi, const __nv_bfloat16* __restrict__ qlo,
    const __nv_bfloat16* __restrict__ khi, const __nv_bfloat16* __restrict__ klo,
    const __nv_bfloat16* __restrict__ vhi, const __nv_bfloat16* __restrict__ vlo,
    __nv_bfloat16* __restrict__ ahi_out, __nv_bfloat16* __restrict__ alo_out)
{
    extern __shared__ __nv_bfloat16 smf[];
    uint32_t usm = s2u(smf);
    __nv_bfloat16* Qh = smf;
    __nv_bfloat16* Ql = smf + FQ64;

    int tid = threadIdx.x;
    int wm = tid >> 5, lane = tid & 31;
    int gid = lane >> 2, tig = lane & 3;
    int qb = (gridDim.x - 1) - blockIdx.x;
    int h = blockIdx.y;
    int kvh = h >> 2;

#pragma unroll
    for (int i = 0; i < 8; i++) {
        int idx = tid + 128 * i;
        int r = idx >> 4, c8 = (idx & 15) * 8;
        size_t src = ((size_t)(qb * 64 + r) * 32 + h) * 128 + c8;
        *(uint4*)&Qh[r * LDH + c8] = *(const uint4*)&qhi[src];
        *(uint4*)&Ql[r * LDH + c8] = *(const uint4*)&qlo[src];
    }

    uint32_t kv_goff[4], kv_soff[4];
#pragma unroll
    for (int i = 0; i < 4; i++) {
        int idx = tid + 128 * i;
        int r = idx >> 4, c8 = (idx & 15) * 8;
        kv_goff[i] = (uint32_t)(r * (NKVH * HDIM) + kvh * HDIM + c8);
        kv_soff[i] = (uint32_t)(r * LDH + c8) * 2;
    }

    int nkb = 2 * (qb + 1);

#define F_ISSUE(kb, s)                                                        \
    {                                                                         \
        uint32_t sb = usm + (2 * FQ64 + (s) * 4 * FT32) * 2;                  \
        size_t tb = (size_t)(kb) * 32 * (NKVH * HDIM);                        \
        _Pragma("unroll")                                                     \
        for (int i = 0; i < 4; i++) {                                         \
            cp16(sb + kv_soff[i],            khi + tb + kv_goff[i]);          \
            cp16(sb + FT32*2 + kv_soff[i],   klo + tb + kv_goff[i]);          \
            cp16(sb + 2*FT32*2 + kv_soff[i], vhi + tb + kv_goff[i]);          \
            cp16(sb + 3*FT32*2 + kv_soff[i], vlo + tb + kv_goff[i]);          \
        }                                                                     \
    }

    F_ISSUE(0, 0); CP_COMMIT();

    int mi = lane >> 3, lr = lane & 7;
    uint32_t offQ = (uint32_t)((16 * wm + (mi & 1) * 8 + lr) * LDH + (mi >> 1) * 8) * 2;
    uint32_t offK = (uint32_t)(((mi >> 1) * 8 + lr) * LDH + (mi & 1) * 8) * 2;
    uint32_t offV = (uint32_t)(((mi & 1) * 8 + lr) * LDH + (mi >> 1) * 8) * 2;
    uint32_t uQh = usm, uQl = usm + FQ64 * 2;

    float O[16][4];
#pragma unroll
    for (int nt = 0; nt < 16; nt++)
#pragma unroll
        for (int e = 0; e < 4; e++) O[nt][e] = 0.f;

    float m0 = -1e30f, m1 = -1e30f, l0 = 0.f, l1 = 0.f;
    int qg0 = qb * 64 + wm * 16 + gid;
    int qg1 = qg0 + 8;
    const float scale = 0.08838834764831845f;

    for (int kb = 0; kb < nkb; kb++) {
        CP_WAIT0();
        __syncthreads();
        if (kb + 1 < nkb) { F_ISSUE(kb + 1, (kb + 1) & 1); CP_COMMIT(); }

        uint32_t sb = usm + (2 * FQ64 + (kb & 1) * 4 * FT32) * 2;
        uint32_t uKh = sb, uKl = sb + FT32 * 2;
        uint32_t uVh = sb + 2 * FT32 * 2, uVl = sb + 3 * FT32 * 2;

        float S[4][4];
#pragma unroll
        for (int nt = 0; nt < 4; nt++)
#pragma unroll
            for (int e = 0; e < 4; e++) S[nt][e] = 0.f;

#pragma unroll
        for (int ks = 0; ks < 8; ks++) {
            uint32_t qh4[4], ql4[4];
            ldsm4(qh4, uQh + offQ + ks * 32);
            ldsm4(ql4, uQl + offQ + ks * 32);
#pragma unroll
            for (int ntp = 0; ntp < 2; ntp++) {
                uint32_t kh4[4], kl4[4];
                ldsm4(kh4, uKh + offK + ntp * (16 * LDH * 2) + ks * 32);
                ldsm4(kl4, uKl + offK + ntp * (16 * LDH * 2) + ks * 32);
                mma16816(S[2 * ntp],     qh4, kh4);
                mma16816(S[2 * ntp + 1], qh4, kh4 + 2);
                mma16816(S[2 * ntp],     qh4, kl4);
                mma16816(S[2 * ntp + 1], qh4, kl4 + 2);
                mma16816(S[2 * ntp],     ql4, kh4);
                mma16816(S[2 * ntp + 1], ql4, kh4 + 2);
            }
        }

        int kvb = kb * 32;
        float rmax0 = -1e30f, rmax1 = -1e30f;
#pragma unroll
        for (int nt = 0; nt < 4; nt++) {
            int kg = kvb + nt * 8 + tig * 2;
            float s0 = (kg     <= qg0) ? S[nt][0] * scale : -1e30f;
            float s1 = (kg + 1 <= qg0) ? S[nt][1] * scale : -1e30f;
            float s2 = (kg     <= qg1) ? S[nt][2] * scale : -1e30f;
            float s3 = (kg + 1 <= qg1) ? S[nt][3] * scale : -1e30f;
            S[nt][0] = s0; S[nt][1] = s1; S[nt][2] = s2; S[nt][3] = s3;
            rmax0 = fmaxf(rmax0, fmaxf(s0, s1));
            rmax1 = fmaxf(rmax1, fmaxf(s2, s3));
        }
        rmax0 = fmaxf(rmax0, __shfl_xor_sync(0xffffffffu, rmax0, 1));
        rmax0 = fmaxf(rmax0, __shfl_xor_sync(0xffffffffu, rmax0, 2));
        rmax1 = fmaxf(rmax1, __shfl_xor_sync(0xffffffffu, rmax1, 1));
        rmax1 = fmaxf(rmax1, __shfl_xor_sync(0xffffffffu, rmax1, 2));

        float mn0 = fmaxf(m0, rmax0), mn1 = fmaxf(m1, rmax1);
        float f0 = __expf(m0 - mn0), f1 = __expf(m1 - mn1);
        m0 = mn0; m1 = mn1;

        float ls0 = 0.f, ls1 = 0.f;
#pragma unroll
        for (int nt = 0; nt < 4; nt++) {
            float p0 = __expf(S[nt][0] - mn0);
            float p1 = __expf(S[nt][1] - mn0);
            float p2 = __expf(S[nt][2] - mn1);
            float p3 = __expf(S[nt][3] - mn1);
            S[nt][0] = p0; S[nt][1] = p1; S[nt][2] = p2; S[nt][3] = p3;
            ls0 += p0 + p1; ls1 += p2 + p3;
        }
        ls0 += __shfl_xor_sync(0xffffffffu, ls0, 1);
        ls0 += __shfl_xor_sync(0xffffffffu, ls0, 2);
        ls1 += __shfl_xor_sync(0xffffffffu, ls1, 1);
        ls1 += __shfl_xor_sync(0xffffffffu, ls1, 2);
        l0 = l0 * f0 + ls0;
        l1 = l1 * f1 + ls1;

#pragma unroll
        for (int nt = 0; nt < 16; nt++) {
            O[nt][0] *= f0; O[nt][1] *= f0;
            O[nt][2] *= f1; O[nt][3] *= f1;
        }

#pragma unroll
        for (int ks2 = 0; ks2 < 2; ks2++) {
            uint32_t ahi[4], alo[4];
            split2(S[2 * ks2][0],     S[2 * ks2][1],     ahi[0], alo[0]);
            split2(S[2 * ks2][2],     S[2 * ks2][3],     ahi[1], alo[1]);
            split2(S[2 * ks2 + 1][0], S[2 * ks2 + 1][1], ahi[2], alo[2]);
            split2(S[2 * ks2 + 1][2], S[2 * ks2 + 1][3], ahi[3], alo[3]);
#pragma unroll
            for (int ntp = 0; ntp < 8; ntp++) {
                uint32_t vh4[4], vl4[4];
                ldsm4t(vh4, uVh + offV + ks2 * (16 * LDH * 2) + ntp * 32);
                ldsm4t(vl4, uVl + offV + ks2 * (16 * LDH * 2) + ntp * 32);
                mma16816(O[2 * ntp],     ahi, vh4);
                mma16816(O[2 * ntp + 1], ahi, vh4 + 2);
                mma16816(O[2 * ntp],     ahi, vl4);
                mma16816(O[2 * ntp + 1], ahi, vl4 + 2);
                mma16816(O[2 * ntp],     alo, vh4);
                mma16816(O[2 * ntp + 1], alo, vh4 + 2);
            }
        }
    }

    float inv0 = 1.f / l0, inv1 = 1.f / l1;
    size_t ob0 = (size_t)(qb * 64 + wm * 16 + gid) * HID + (size_t)h * HDIM;
    size_t ob1 = ob0 + 8 * (size_t)HID;
#pragma unroll
    for (int nt = 0; nt < 16; nt++) {
        int col = nt * 8 + tig * 2;
        uint32_t hh, ll;
        split2(O[nt][0] * inv0, O[nt][1] * inv0, hh, ll);
        *(uint32_t*)&ahi_out[ob0 + col] = hh;
        *(uint32_t*)&alo_out[ob0 + col] = ll;
        split2(O[nt][2] * inv1, O[nt][3] * inv1, hh, ll);
        *(uint32_t*)&ahi_out[ob1 + col] = hh;
        *(uint32_t*)&alo_out[ob1 + col] = ll;
    }
}

// =====================================================================
// Host orchestration — multi-stream fork/join (graph-capturable)
// =====================================================================
static void convS(cudaStream_t st, const void* in, __nv_bfloat16* hi,
                  __nv_bfloat16* lo, size_t n) {
    int n4 = (int)(n / 4);
    int blocks = (n4 + 255) / 256;
    if (blocks > 6144) blocks = 6144;
    conv_split<<<blocks, 256, 0, st>>>((const float4*)in, hi, lo, n4);
}

#define SYM(v, s) cudaGetSymbolAddress((void**)&v, s)

extern "C" void kernel_launch(void* const* d_in, const int* in_sizes, int n_in,
                              void* d_out, int out_size)
{
    const float* hs     = (const float*)d_in[0];
    const float* cosp   = (const float*)d_in[1];
    const float* sinp   = (const float*)d_in[2];
    const float* bcos   = (const float*)d_in[3];
    const float* bsin   = (const float*)d_in[4];
    const int*   memidx = (const int*)d_in[5];
    const int*   imidx  = (const int*)d_in[6];
    const float* kc_in  = (const float*)d_in[7];
    const float* vc_in  = (const float*)d_in[8];
    const int*   blkoff = (const int*)d_in[9];
    const float* wqkv_w = (const float*)d_in[10];
    const float* wqkv_A = (const float*)d_in[11];
    const float* wqkv_B = (const float*)d_in[12];
    const float* wqkv_MA= (const float*)d_in[13];
    const float* wqkv_MB= (const float*)d_in[14];
    const float* wo_w   = (const float*)d_in[15];
    const float* wo_A   = (const float*)d_in[16];
    const float* wo_B   = (const float*)d_in[17];
    const float* wo_MA  = (const float*)d_in[18];
    const float* wo_MB  = (const float*)d_in[19];

    float* outp   = (float*)d_out;
    float* kc_out = outp + (size_t)TT * HID;
    float* vc_out = kc_out + CACHE_ELEMS;

    float *qkv;
    SYM(qkv, g_qkv);

    __nv_bfloat16 *hs_hi,*hs_lo,*attn_hi,*attn_lo,*q_hi,*q_lo,*k_hi,*k_lo,*v_hi,*v_lo;
    __nv_bfloat16 *tim_hi,*tim_lo,*tmem_hi,*tmem_lo;
    __nv_bfloat16 *wqkv_hi,*wqkv_lo,*wqA_hi,*wqA_lo,*wqB_hi,*wqB_lo,*wqMA_hi,*wqMA_lo,*wqMB_hi,*wqMB_lo;
    __nv_bfloat16 *wo_hi,*wo_lo,*woA_hi,*woA_lo,*woB_hi,*woB_lo,*woMA_hi,*woMA_lo,*woMB_hi,*woMB_lo;
    SYM(hs_hi, g_hs_hi);     SYM(hs_lo, g_hs_lo);
    SYM(attn_hi, g_attn_hi); SYM(attn_lo, g_attn_lo);
    SYM(q_hi, g_q_hi);       SYM(q_lo, g_q_lo);
    SYM(k_hi, g_k_hi);       SYM(k_lo, g_k_lo);
    SYM(v_hi, g_v_hi);       SYM(v_lo, g_v_lo);
    SYM(tim_hi, g_tim_hi);   SYM(tim_lo, g_tim_lo);
    SYM(tmem_hi, g_tmem_hi); SYM(tmem_lo, g_tmem_lo);
    SYM(wqkv_hi, g_wqkv_hi); SYM(wqkv_lo, g_wqkv_lo);
    SYM(wqA_hi, g_wqA_hi);   SYM(wqA_lo, g_wqA_lo);
    SYM(wqB_hi, g_wqB_hi);   SYM(wqB_lo, g_wqB_lo);
    SYM(wqMA_hi, g_wqMA_hi); SYM(wqMA_lo, g_wqMA_lo);
    SYM(wqMB_hi, g_wqMB_hi); SYM(wqMB_lo, g_wqMB_lo);
    SYM(wo_hi, g_wo_hi);     SYM(wo_lo, g_wo_lo);
    SYM(woA_hi, g_woA_hi);   SYM(woA_lo, g_woA_lo);
    SYM(woB_hi, g_woB_hi);   SYM(woB_lo, g_woB_lo);
    SYM(woMA_hi, g_woMA_hi); SYM(woMA_lo, g_woMA_lo);
    SYM(woMB_hi, g_woMB_hi); SYM(woMB_lo, g_woMB_lo);

    cudaFuncSetAttribute(gemm_hl, cudaFuncAttributeMaxDynamicSharedMemorySize, GEMM_SMEM);
    cudaFuncSetAttribute(flash_mma, cudaFuncAttributeMaxDynamicSharedMemorySize, FA3_SMEM);

    cudaStream_t s1, s2;
    cudaStreamCreateWithFlags(&s1, cudaStreamNonBlocking);
    cudaStreamCreateWithFlags(&s2, cudaStreamNonBlocking);
    cudaEvent_t eFork, eHs, eWqA, eWqB, eQKV, eCpy, eWoC, eQall, eFlash, eWoA, eS1, eS2;
    cudaEvent_t* evs[12] = {&eFork,&eHs,&eWqA,&eWqB,&eQKV,&eCpy,&eWoC,&eQall,&eFlash,&eWoA,&eS1,&eS2};
    for (int i = 0; i < 12; i++) cudaEventCreateWithFlags(evs[i], cudaEventDisableTiming);

    // ---- fork immediately: conversions run concurrently ----
    cudaEventRecord(eFork, 0);
    cudaStreamWaitEvent(s1, eFork, 0);
    cudaStreamWaitEvent(s2, eFork, 0);

    // origin: the big weight conversion (critical path for QKV gemm)
    convS(0, wqkv_w, wqkv_hi, wqkv_lo, (size_t)QKVO * HID);

    // s1: hs + LoRA-A weights concurrently with wqkv conv
    convS(s1, hs, hs_hi, hs_lo, (size_t)TT * HID);
    cudaEventRecord(eHs, s1);
    convS(s1, wqkv_A, wqA_hi, wqA_lo, (size_t)RANK * HID);
    convS(s1, wqkv_MA, wqMA_hi, wqMA_lo, (size_t)RANK * HID);
    cudaEventRecord(eWqA, s1);
    convS(s1, wqkv_B, wqB_hi, wqB_lo, (size_t)QKVO * RANK);
    convS(s1, wqkv_MB, wqMB_hi, wqMB_lo, (size_t)QKVO * RANK);
    cudaEventRecord(eWqB, s1);

    // origin: QKV main projection (needs wqkv conv [program order] + hs conv)
    cudaStreamWaitEvent(0, eHs, 0);
    gemm_hl<<<dim3(QKVO/128, TT/128), 256, GEMM_SMEM>>>(hs_hi, hs_lo, wqkv_hi, wqkv_lo,
        qkv, nullptr, nullptr, TT, QKVO, HID, nullptr, nullptr);
    cudaEventRecord(eQKV, 0);

    // s1: cache memcpys + WO-side conversions
    cudaMemcpyAsync(kc_out, kc_in, (size_t)CACHE_ELEMS * sizeof(float),
                    cudaMemcpyDeviceToDevice, s1);
    cudaMemcpyAsync(vc_out, vc_in, (size_t)CACHE_ELEMS * sizeof(float),
                    cudaMemcpyDeviceToDevice, s1);
    cudaEventRecord(eCpy, s1);
    convS(s1, wo_w, wo_hi, wo_lo, (size_t)HID * HID);
    convS(s1, wo_A, woA_hi, woA_lo, (size_t)RANK * HID);
    convS(s1, wo_MA, woMA_hi, woMA_lo, (size_t)RANK * HID);
    convS(s1, wo_B, woB_hi, woB_lo, (size_t)HID * RANK);
    convS(s1, wo_MB, woMB_hi, woMB_lo, (size_t)HID * RANK);
    cudaEventRecord(eWoC, s1);
    cudaEventRecord(eS1, s1);

    // ---- s2: LoRA for QKV, then cache fill + rope split ----
    cudaStreamWaitEvent(s2, eWqA, 0);
    gemm_hl<<<dim3(RANK/128, NIM/128), 256, GEMM_SMEM, s2>>>(hs_hi, hs_lo, wqA_hi, wqA_lo,
        nullptr, tim_hi, tim_lo, NIM, RANK, HID, imidx, nullptr);
    gemm_hl<<<dim3(RANK/128, NMEM/128), 256, GEMM_SMEM, s2>>>(hs_hi, hs_lo, wqMA_hi, wqMA_lo,
        nullptr, tmem_hi, tmem_lo, NMEM, RANK, HID, memidx, nullptr);
    cudaStreamWaitEvent(s2, eQKV, 0);
    cudaStreamWaitEvent(s2, eWqB, 0);
    gemm_hl<<<dim3(QKVO/128, NIM/128), 256, GEMM_SMEM, s2>>>(tim_hi, tim_lo, wqB_hi, wqB_lo,
        qkv, nullptr, nullptr, NIM, QKVO, RANK, nullptr, imidx);
    gemm_hl<<<dim3(QKVO/128, NMEM/128), 256, GEMM_SMEM, s2>>>(tmem_hi, tmem_lo, wqMB_hi, wqMB_lo,
        qkv, nullptr, nullptr, NMEM, QKVO, RANK, nullptr, memidx);
    cudaStreamWaitEvent(s2, eCpy, 0);
    fill_cache_kernel<<<NMEM, dim3(64, 8), 0, s2>>>(qkv, memidx, blkoff, bcos, bsin, kc_out, vc_out);
    rope_convert<<<dim3(TT, 12), dim3(32, 4), 0, s2>>>(qkv, cosp, sinp, q_hi, q_lo, k_hi, k_lo, v_hi, v_lo);
    cudaEventRecord(eQall, s2);

    // ---- origin: flash attention (single launch, heavy-first) ----
    cudaStreamWaitEvent(0, eQall, 0);
    flash_mma<<<dim3(TT/64, NHEADS), 128, FA3_SMEM>>>(q_hi, q_lo, k_hi, k_lo,
        v_hi, v_lo, attn_hi, attn_lo);
    cudaEventRecord(eFlash, 0);

    // ---- s2: WO LoRA-A (overlaps WO main gemm) ----
    cudaStreamWaitEvent(s2, eFlash, 0);
    cudaStreamWaitEvent(s2, eWoC, 0);
    gemm_hl<<<dim3(RANK/128, NIM/128), 256, GEMM_SMEM, s2>>>(attn_hi, attn_lo, woA_hi, woA_lo,
        nullptr, tim_hi, tim_lo, NIM, RANK, HID, imidx, nullptr);
    gemm_hl<<<dim3(RANK/128, NMEM/128), 256, GEMM_SMEM, s2>>>(attn_hi, attn_lo, woMA_hi, woMA_lo,
        nullptr, tmem_hi, tmem_lo, NMEM, RANK, HID, memidx, nullptr);
    cudaEventRecord(eWoA, s2);
    cudaEventRecord(eS2, s2);

    // ---- origin: WO main projection + LoRA-B scatter ----
    cudaStreamWaitEvent(0, eWoC, 0);
    gemm_hl<<<dim3(HID/128, TT/128), 256, GEMM_SMEM>>>(attn_hi, attn_lo, wo_hi, wo_lo,
        outp, nullptr, nullptr, TT, HID, HID, nullptr, nullptr);
    cudaStreamWaitEvent(0, eWoA, 0);
    gemm_hl<<<dim3(HID/128, NIM/128), 256, GEMM_SMEM>>>(tim_hi, tim_lo, woB_hi, woB_lo,
        outp, nullptr, nullptr, NIM, HID, RANK, nullptr, imidx);
    gemm_hl<<<dim3(HID/128, NMEM/128), 256, GEMM_SMEM>>>(tmem_hi, tmem_lo, woMB_hi, woMB_lo,
        outp, nullptr, nullptr, NMEM, HID, RANK, nullptr, memidx);

    // ---- join forked streams back into origin ----
    cudaStreamWaitEvent(0, eS1, 0);
    cudaStreamWaitEvent(0, eS2, 0);

    cudaStreamCaptureStatus st = cudaStreamCaptureStatusNone;
    cudaStreamIsCapturing(0, &st);
    if (st == cudaStreamCaptureStatusNone) {
        for (int i = 0; i < 12; i++) cudaEventDestroy(*evs[i]);
        cudaStreamDestroy(s1);
        cudaStreamDestroy(s2);
    }
}

// round 16
// speedup vs baseline: 1.1005x; 1.0010x over previous
#include <cuda_runtime.h>
#include <cuda_bf16.h>
#include <math.h>
#include <float.h>
#include <stdint.h>

#define TT     2048
#define HID    4096
#define NHEADS 32
#define NKVH   8
#define HDIM   128
#define QKVO   6144
#define RANK   256
#define NIM    512
#define NMEM   128
#define CACHE_ELEMS (4*64*NKVH*HDIM)

// ---------------- scratch ----------------
__device__ float g_qkv[TT * QKVO];

__device__ __nv_bfloat16 g_hs_hi[TT*HID],    g_hs_lo[TT*HID];
__device__ __nv_bfloat16 g_attn_hi[TT*HID],  g_attn_lo[TT*HID];
__device__ __nv_bfloat16 g_q_hi[TT*HID],     g_q_lo[TT*HID];
__device__ __nv_bfloat16 g_k_hi[TT*NKVH*HDIM], g_k_lo[TT*NKVH*HDIM];
__device__ __nv_bfloat16 g_v_hi[TT*NKVH*HDIM], g_v_lo[TT*NKVH*HDIM];
__device__ __nv_bfloat16 g_tim_hi[NIM*RANK],  g_tim_lo[NIM*RANK];
__device__ __nv_bfloat16 g_tmem_hi[NMEM*RANK], g_tmem_lo[NMEM*RANK];

__device__ __nv_bfloat16 g_wqkv_hi[QKVO*HID], g_wqkv_lo[QKVO*HID];
__device__ __nv_bfloat16 g_wqA_hi[RANK*HID],  g_wqA_lo[RANK*HID];
__device__ __nv_bfloat16 g_wqB_hi[QKVO*RANK], g_wqB_lo[QKVO*RANK];
__device__ __nv_bfloat16 g_wqMA_hi[RANK*HID], g_wqMA_lo[RANK*HID];
__device__ __nv_bfloat16 g_wqMB_hi[QKVO*RANK],g_wqMB_lo[QKVO*RANK];
__device__ __nv_bfloat16 g_wo_hi[HID*HID],    g_wo_lo[HID*HID];
__device__ __nv_bfloat16 g_woA_hi[RANK*HID],  g_woA_lo[RANK*HID];
__device__ __nv_bfloat16 g_woB_hi[HID*RANK],  g_woB_lo[HID*RANK];
__device__ __nv_bfloat16 g_woMA_hi[RANK*HID], g_woMA_lo[RANK*HID];
__device__ __nv_bfloat16 g_woMB_hi[HID*RANK], g_woMB_lo[HID*RANK];

// ---------------- helpers ----------------
__device__ __forceinline__ uint32_t pack_bf16(float x, float y) {
    __nv_bfloat162 t = __floats2bfloat162_rn(x, y);
    return *reinterpret_cast<uint32_t*>(&t);
}
__device__ __forceinline__ void split2(float x, float y, uint32_t& h, uint32_t& l) {
    float hx = __bfloat162float(__float2bfloat16(x));
    float hy = __bfloat162float(__float2bfloat16(y));
    h = pack_bf16(x, y);
    l = pack_bf16(x - hx, y - hy);
}
__device__ __forceinline__ void mma16816(float* c, const uint32_t* a, const uint32_t* b) {
    asm volatile(
        "mma.sync.aligned.m16n8k16.row.col.f32.bf16.bf16.f32 "
        "{%0,%1,%2,%3}, {%4,%5,%6,%7}, {%8,%9}, {%0,%1,%2,%3};\n"
        : "+f"(c[0]), "+f"(c[1]), "+f"(c[2]), "+f"(c[3])
        : "r"(a[0]), "r"(a[1]), "r"(a[2]), "r"(a[3]), "r"(b[0]), "r"(b[1]));
}
__device__ __forceinline__ uint32_t s2u(const void* p) {
    return (uint32_t)__cvta_generic_to_shared(p);
}
__device__ __forceinline__ void cp16(uint32_t saddr, const void* gaddr) {
    asm volatile("cp.async.cg.shared.global [%0], [%1], 16;\n" :: "r"(saddr), "l"(gaddr));
}
#define CP_COMMIT() asm volatile("cp.async.commit_group;\n")
#define CP_WAIT0()  asm volatile("cp.async.wait_group 0;\n")
__device__ __forceinline__ void ldsm4(uint32_t* r, uint32_t saddr) {
    asm volatile("ldmatrix.sync.aligned.m8n8.x4.shared.b16 {%0,%1,%2,%3}, [%4];\n"
        : "=r"(r[0]), "=r"(r[1]), "=r"(r[2]), "=r"(r[3]) : "r"(saddr));
}
__device__ __forceinline__ void ldsm4t(uint32_t* r, uint32_t saddr) {
    asm volatile("ldmatrix.sync.aligned.m8n8.x4.trans.shared.b16 {%0,%1,%2,%3}, [%4];\n"
        : "=r"(r[0]), "=r"(r[1]), "=r"(r[2]), "=r"(r[3]) : "r"(saddr));
}

// ---------------- split conversion ----------------
__global__ void conv_split(const float4* __restrict__ in,
                           __nv_bfloat16* __restrict__ hi,
                           __nv_bfloat16* __restrict__ lo, int n4)
{
    int i = blockIdx.x * blockDim.x + threadIdx.x;
    int stride = gridDim.x * blockDim.x;
    for (; i < n4; i += stride) {
        float4 v = in[i];
        uint32_t h0, l0, h1, l1;
        split2(v.x, v.y, h0, l0);
        split2(v.z, v.w, h1, l1);
        *(uint32_t*)&hi[4*i]     = h0;
        *(uint32_t*)&hi[4*i + 2] = h1;
        *(uint32_t*)&lo[4*i]     = l0;
        *(uint32_t*)&lo[4*i + 2] = l1;
    }
}

// fused RoPE + hi/lo split: reads RAW qkv f32 (does NOT modify it)
// grid (TT, 12), block (32, 4)
__global__ void rope_convert(const float* __restrict__ qkv,
    const float* __restrict__ cosp, const float* __restrict__ sinp,
    __nv_bfloat16* __restrict__ qh, __nv_bfloat16* __restrict__ ql,
    __nv_bfloat16* __restrict__ kh, __nv_bfloat16* __restrict__ kl,
    __nv_bfloat16* __restrict__ vh, __nv_bfloat16* __restrict__ vl)
{
    int t = blockIdx.x;
    int hh = blockIdx.y * 4 + threadIdx.y;
    int d4 = threadIdx.x * 4;
    int srcoff;
    __nv_bfloat16 *dh, *dl;
    size_t dst;
    bool dorope = true;
    if (hh < 32) {
        srcoff = (hh >> 2) * 768 + (hh & 3) * 128;
        dh = qh; dl = ql;
        dst = ((size_t)t * 32 + hh) * 128 + d4;
    } else if (hh < 40) {
        srcoff = (hh - 32) * 768 + 512;
        dh = kh; dl = kl;
        dst = ((size_t)t * 8 + (hh - 32)) * 128 + d4;
    } else {
        srcoff = (hh - 40) * 768 + 640;
        dh = vh; dl = vl;
        dst = ((size_t)t * 8 + (hh - 40)) * 128 + d4;
        dorope = false;
    }
    const float* src = qkv + (size_t)t * QKVO + srcoff;
    float o[4];
    if (dorope) {
        const float* c = cosp + (size_t)t * HDIM;
        const float* s = sinp + (size_t)t * HDIM;
        float4 x  = *(const float4*)(src + d4);
        int p4 = (d4 < 64) ? d4 + 64 : d4 - 64;
        float4 xp = *(const float4*)(src + p4);
        float sg = (d4 < 64) ? -1.f : 1.f;
        o[0] = x.x * c[d4+0] + sg * xp.x * s[d4+0];
        o[1] = x.y * c[d4+1] + sg * xp.y * s[d4+1];
        o[2] = x.z * c[d4+2] + sg * xp.z * s[d4+2];
        o[3] = x.w * c[d4+3] + sg * xp.w * s[d4+3];
    } else {
        float4 x = *(const float4*)(src + d4);
        o[0] = x.x; o[1] = x.y; o[2] = x.z; o[3] = x.w;
    }
    uint32_t h0, l0, h1, l1;
    split2(o[0], o[1], h0, l0);
    split2(o[2], o[3], h1, l1);
    *(uint32_t*)&dh[dst]     = h0;
    *(uint32_t*)&dh[dst + 2] = h1;
    *(uint32_t*)&dl[dst]     = l0;
    *(uint32_t*)&dl[dst + 2] = l1;
}

// =====================================================================
// Pipelined hi/lo GEMM — 2-stage, 2 CTAs/SM, L2 swizzle
// =====================================================================
#define LDKS 40
#define GTS (128 * LDKS)
#define GSTAGE (4 * GTS * 2)
#define GEMM_SMEM (2 * GSTAGE)

__global__ __launch_bounds__(256, 2) void gemm_hl(
    const __nv_bfloat16* __restrict__ Ahi, const __nv_bfloat16* __restrict__ Alo,
    const __nv_bfloat16* __restrict__ Bhi, const __nv_bfloat16* __restrict__ Blo,
    float* __restrict__ C, __nv_bfloat16* __restrict__ Chi, __nv_bfloat16* __restrict__ Clo,
    int M, int N, int K, const int* __restrict__ gatherA,
    const int* __restrict__ scatterC)
{
    extern __shared__ __nv_bfloat16 smg[];
    uint32_t usm = s2u(smg);

    int tid = threadIdx.x;
    int bm, bn;
    {
        int G = (gridDim.x < 8) ? gridDim.x : 8;
        if (gridDim.x % G) { bn = blockIdx.x; bm = blockIdx.y; }
        else {
            int idb = blockIdx.y * gridDim.x + blockIdx.x;
            int gsz = G * gridDim.y;
            int grp = idb / gsz;
            int rem = idb - grp * gsz;
            bn = grp * G + rem % G;
            bm = rem / G;
        }
    }
    int warp = tid >> 5, lane = tid & 31;
    int wm = warp & 1, wn = warp >> 1;
    int gid = lane >> 2, tig = lane & 3;
    int mi = lane >> 3, lr = lane & 7;

    size_t aoff[2], boff[2];
    uint32_t soffB[2];
#pragma unroll
    for (int i = 0; i < 2; i++) {
        int idx = tid + 256 * i;
        int r = idx >> 2;
        int c8 = (idx & 3) * 8;
        int ar = bm * 128 + r;
        if (gatherA) ar = __ldg(&gatherA[ar]);
        aoff[i] = (size_t)ar * K + c8;
        boff[i] = (size_t)(bn * 128 + r) * K + c8;
        soffB[i] = (uint32_t)(r * LDKS + c8) * 2;
    }

    uint32_t offA = (uint32_t)((wm * 64 + (mi & 1) * 8 + lr) * LDKS + (mi >> 1) * 8) * 2;
    uint32_t offB = (uint32_t)((wn * 32 + (mi >> 1) * 8 + lr) * LDKS + (mi & 1) * 8) * 2;

    float acc[4][4][4];
#pragma unroll
    for (int mt = 0; mt < 4; mt++)
#pragma unroll
        for (int nt = 0; nt < 4; nt++)
#pragma unroll
            for (int e = 0; e < 4; e++) acc[mt][nt][e] = 0.f;

    int nk = K / 32;

#define G_ISSUE(s, k0)                                                     \
    {                                                                      \
        uint32_t sb = usm + (uint32_t)(s) * GSTAGE;                        \
        _Pragma("unroll")                                                  \
        for (int i = 0; i < 2; i++) {                                      \
            cp16(sb + soffB[i],             Ahi + aoff[i] + (k0));         \
            cp16(sb + GTS*2 + soffB[i],     Alo + aoff[i] + (k0));         \
            cp16(sb + 2*GTS*2 + soffB[i],   Bhi + boff[i] + (k0));         \
            cp16(sb + 3*GTS*2 + soffB[i],   Blo + boff[i] + (k0));         \
        }                                                                  \
    }

    G_ISSUE(0, 0); CP_COMMIT();

    for (int t = 0; t < nk; t++) {
        CP_WAIT0();
        __syncthreads();
        if (t + 1 < nk) { G_ISSUE((t + 1) & 1, (t + 1) * 32); CP_COMMIT(); }

        uint32_t sb = usm + (uint32_t)(t & 1) * GSTAGE;
        uint32_t uAh = sb, uAl = sb + GTS * 2;
        uint32_t uBh = sb + 2 * GTS * 2, uBl = sb + 3 * GTS * 2;

#pragma unroll
        for (int kb = 0; kb < 64; kb += 32) {
            uint32_t ah[4][4], al[4][4];
            uint32_t bh[2][4], bl[2][4];
#pragma unroll
            for (int mt = 0; mt < 4; mt++) {
                ldsm4(ah[mt], uAh + offA + mt * (16 * LDKS * 2) + kb);
                ldsm4(al[mt], uAl + offA + mt * (16 * LDKS * 2) + kb);
            }
#pragma unroll
            for (int nn = 0; nn < 2; nn++) {
                ldsm4(bh[nn], uBh + offB + nn * (16 * LDKS * 2) + kb);
                ldsm4(bl[nn], uBl + offB + nn * (16 * LDKS * 2) + kb);
            }
#pragma unroll
            for (int nt = 0; nt < 4; nt++) {
                const uint32_t* bf = bh[nt >> 1] + (nt & 1) * 2;
#pragma unroll
                for (int mt = 0; mt < 4; mt++)
                    mma16816(acc[mt][nt], ah[mt], bf);
            }
#pragma unroll
            for (int nt = 0; nt < 4; nt++) {
                const uint32_t* bf = bl[nt >> 1] + (nt & 1) * 2;
#pragma unroll
                for (int mt = 0; mt < 4; mt++)
                    mma16816(acc[mt][nt], ah[mt], bf);
            }
#pragma unroll
            for (int nt = 0; nt < 4; nt++) {
                const uint32_t* bf = bh[nt >> 1] + (nt & 1) * 2;
#pragma unroll
                for (int mt = 0; mt < 4; mt++)
                    mma16816(acc[mt][nt], al[mt], bf);
            }
        }
    }

    if (scatterC) {
#pragma unroll
        for (int mt = 0; mt < 4; mt++) {
            int r0 = bm * 128 + wm * 64 + mt * 16 + gid;
            int rr0 = __ldg(&scatterC[r0]);
            int rr1 = __ldg(&scatterC[r0 + 8]);
#pragma unroll
            for (int nt = 0; nt < 4; nt++) {
                int c0 = bn * 128 + wn * 32 + nt * 8 + tig * 2;
                atomicAdd(&C[(size_t)rr0 * N + c0],     acc[mt][nt][0]);
                atomicAdd(&C[(size_t)rr0 * N + c0 + 1], acc[mt][nt][1]);
                atomicAdd(&C[(size_t)rr1 * N + c0],     acc[mt][nt][2]);
                atomicAdd(&C[(size_t)rr1 * N + c0 + 1], acc[mt][nt][3]);
            }
        }
    } else if (C) {
#pragma unroll
        for (int mt = 0; mt < 4; mt++) {
            int r0 = bm * 128 + wm * 64 + mt * 16 + gid;
#pragma unroll
            for (int nt = 0; nt < 4; nt++) {
                int c0 = bn * 128 + wn * 32 + nt * 8 + tig * 2;
                *(float2*)&C[(size_t)r0 * N + c0] =
                    make_float2(acc[mt][nt][0], acc[mt][nt][1]);
                *(float2*)&C[(size_t)(r0 + 8) * N + c0] =
                    make_float2(acc[mt][nt][2], acc[mt][nt][3]);
            }
        }
    } else {
#pragma unroll
        for (int mt = 0; mt < 4; mt++) {
            int r0 = bm * 128 + wm * 64 + mt * 16 + gid;
#pragma unroll
            for (int nt = 0; nt < 4; nt++) {
                int c0 = bn * 128 + wn * 32 + nt * 8 + tig * 2;
                uint32_t h, l;
                split2(acc[mt][nt][0], acc[mt][nt][1], h, l);
                *(uint32_t*)&Chi[(size_t)r0 * N + c0] = h;
                *(uint32_t*)&Clo[(size_t)r0 * N + c0] = l;
                split2(acc[mt][nt][2], acc[mt][nt][3], h, l);
                *(uint32_t*)&Chi[(size_t)(r0 + 8) * N + c0] = h;
                *(uint32_t*)&Clo[(size_t)(r0 + 8) * N + c0] = l;
            }
        }
    }
}

// ---------------- KV-cache fill (reads qkv incl. LoRA) ----------------
__global__ void fill_cache_kernel(const float* __restrict__ qkv,
                                  const int* __restrict__ mem_idx,
                                  const int* __restrict__ blkoff,
                                  const float* __restrict__ bcos,
                                  const float* __restrict__ bsin,
                                  float* __restrict__ kc, float* __restrict__ vc)
{
    int m = blockIdx.x;
    int h = threadIdx.y;
    int d = threadIdx.x;
    int tok = mem_idx[m];
    int blk = blkoff[m >> 6];
    int off = m & 63;
    const float* kb = qkv + (size_t)tok * QKVO + (size_t)(h * 6 + 4) * HDIM;
    const float* vb = qkv + (size_t)tok * QKVO + (size_t)(h * 6 + 5) * HDIM;
    size_t dsti = (((size_t)(blk * 64 + off)) * NKVH + h) * HDIM;
    const float* c = bcos + (size_t)m * HDIM;
    const float* s = bsin + (size_t)m * HDIM;
    float x1 = kb[d], x2 = kb[d + 64];
    kc[dsti + d]      = x1 * c[d]      - x2 * s[d];
    kc[dsti + d + 64] = x2 * c[d + 64] + x1 * s[d + 64];
    vc[dsti + d]      = vb[d];
    vc[dsti + d + 64] = vb[d + 64];
}

// =====================================================================
// Flash attention (mma.sync), causal, GQA 4:1.
// BM=64 (4 warps), KV tile 32, 2 CTAs/SM. Heavy q-blocks first.
// =====================================================================
#define LDH  136
#define FQ64 (64 * LDH)
#define FT32 (32 * LDH)
#define FA3_SMEM ((2 * FQ64 + 2 * 4 * FT32) * 2)

__global__ __launch_bounds__(128, 2) void flash_mma(
    const __nv_bfloat16* __restrict__ qhi, const __nv_bfloat16* __restrict__ qlo,
    const __nv_bfloat16* __restrict__ khi, const __nv_bfloat16* __restrict__ klo,
    const __nv_bfloat16* __restrict__ vhi, const __nv_bfloat16* __restrict__ vlo,
    __nv_bfloat16* __restrict__ ahi_out, __nv_bfloat16* __restrict__ alo_out)
{
    extern __shared__ __nv_bfloat16 smf[];
    uint32_t usm = s2u(smf);
    __nv_bfloat16* Qh = smf;
    __nv_bfloat16* Ql = smf + FQ64;

    int tid = threadIdx.x;
    int wm = tid >> 5, lane = tid & 31;
    int gid = lane >> 2, tig = lane & 3;
    int qb = (gridDim.x - 1) - blockIdx.x;
    int h = blockIdx.y;
    int kvh = h >> 2;

#pragma unroll
    for (int i = 0; i < 8; i++) {
        int idx = tid + 128 * i;
        int r = idx >> 4, c8 = (idx & 15) * 8;
        size_t src = ((size_t)(qb * 64 + r) * 32 + h) * 128 + c8;
        *(uint4*)&Qh[r * LDH + c8] = *(const uint4*)&qhi[src];
        *(uint4*)&Ql[r * LDH + c8] = *(const uint4*)&qlo[src];
    }

    uint32_t kv_goff[4], kv_soff[4];
#pragma unroll
    for (int i = 0; i < 4; i++) {
        int idx = tid + 128 * i;
        int r = idx >> 4, c8 = (idx & 15) * 8;
        kv_goff[i] = (uint32_t)(r * (NKVH * HDIM) + kvh * HDIM + c8);
        kv_soff[i] = (uint32_t)(r * LDH + c8) * 2;
    }

    int nkb = 2 * (qb + 1);

#define F_ISSUE(kb, s)                                                        \
    {                                                                         \
        uint32_t sb = usm + (2 * FQ64 + (s) * 4 * FT32) * 2;                  \
        size_t tb = (size_t)(kb) * 32 * (NKVH * HDIM);                        \
        _Pragma("unroll")                                                     \
        for (int i = 0; i < 4; i++) {                                         \
            cp16(sb + kv_soff[i],            khi + tb + kv_goff[i]);          \
            cp16(sb + FT32*2 + kv_soff[i],   klo + tb + kv_goff[i]);          \
            cp16(sb + 2*FT32*2 + kv_soff[i], vhi + tb + kv_goff[i]);          \
            cp16(sb + 3*FT32*2 + kv_soff[i], vlo + tb + kv_goff[i]);          \
        }                                                                     \
    }

    F_ISSUE(0, 0); CP_COMMIT();

    int mi = lane >> 3, lr = lane & 7;
    uint32_t offQ = (uint32_t)((16 * wm + (mi & 1) * 8 + lr) * LDH + (mi >> 1) * 8) * 2;
    uint32_t offK = (uint32_t)(((mi >> 1) * 8 + lr) * LDH + (mi & 1) * 8) * 2;
    uint32_t offV = (uint32_t)(((mi & 1) * 8 + lr) * LDH + (mi >> 1) * 8) * 2;
    uint32_t uQh = usm, uQl = usm + FQ64 * 2;

    float O[16][4];
#pragma unroll
    for (int nt = 0; nt < 16; nt++)
#pragma unroll
        for (int e = 0; e < 4; e++) O[nt][e] = 0.f;

    float m0 = -1e30f, m1 = -1e30f, l0 = 0.f, l1 = 0.f;
    int qg0 = qb * 64 + wm * 16 + gid;
    int qg1 = qg0 + 8;
    const float scale = 0.08838834764831845f;

    for (int kb = 0; kb < nkb; kb++) {
        CP_WAIT0();
        __syncthreads();
        if (kb + 1 < nkb) { F_ISSUE(kb + 1, (kb + 1) & 1); CP_COMMIT(); }

        uint32_t sb = usm + (2 * FQ64 + (kb & 1) * 4 * FT32) * 2;
        uint32_t uKh = sb, uKl = sb + FT32 * 2;
        uint32_t uVh = sb + 2 * FT32 * 2, uVl = sb + 3 * FT32 * 2;

        float S[4][4];
#pragma unroll
        for (int nt = 0; nt < 4; nt++)
#pragma unroll
            for (int e = 0; e < 4; e++) S[nt][e] = 0.f;

#pragma unroll
        for (int ks = 0; ks < 8; ks++) {
            uint32_t qh4[4], ql4[4];
            ldsm4(qh4, uQh + offQ + ks * 32);
            ldsm4(ql4, uQl + offQ + ks * 32);
#pragma unroll
            for (int ntp = 0; ntp < 2; ntp++) {
                uint32_t kh4[4], kl4[4];
                ldsm4(kh4, uKh + offK + ntp * (16 * LDH * 2) + ks * 32);
                ldsm4(kl4, uKl + offK + ntp * (16 * LDH * 2) + ks * 32);
                mma16816(S[2 * ntp],     qh4, kh4);
                mma16816(S[2 * ntp + 1], qh4, kh4 + 2);
                mma16816(S[2 * ntp],     qh4, kl4);
                mma16816(S[2 * ntp + 1], qh4, kl4 + 2);
                mma16816(S[2 * ntp],     ql4, kh4);
                mma16816(S[2 * ntp + 1], ql4, kh4 + 2);
            }
        }

        int kvb = kb * 32;
        float rmax0 = -1e30f, rmax1 = -1e30f;
#pragma unroll
        for (int nt = 0; nt < 4; nt++) {
            int kg = kvb + nt * 8 + tig * 2;
            float s0 = (kg     <= qg0) ? S[nt][0] * scale : -1e30f;
            float s1 = (kg + 1 <= qg0) ? S[nt][1] * scale : -1e30f;
            float s2 = (kg     <= qg1) ? S[nt][2] * scale : -1e30f;
            float s3 = (kg + 1 <= qg1) ? S[nt][3] * scale : -1e30f;
            S[nt][0] = s0; S[nt][1] = s1; S[nt][2] = s2; S[nt][3] = s3;
            rmax0 = fmaxf(rmax0, fmaxf(s0, s1));
            rmax1 = fmaxf(rmax1, fmaxf(s2, s3));
        }
        rmax0 = fmaxf(rmax0, __shfl_xor_sync(0xffffffffu, rmax0, 1));
        rmax0 = fmaxf(rmax0, __shfl_xor_sync(0xffffffffu, rmax0, 2));
        rmax1 = fmaxf(rmax1, __shfl_xor_sync(0xffffffffu, rmax1, 1));
        rmax1 = fmaxf(rmax1, __shfl_xor_sync(0xffffffffu, rmax1, 2));

        float mn0 = fmaxf(m0, rmax0), mn1 = fmaxf(m1, rmax1);
        float f0 = __expf(m0 - mn0), f1 = __expf(m1 - mn1);
        m0 = mn0; m1 = mn1;

        float ls0 = 0.f, ls1 = 0.f;
#pragma unroll
        for (int nt = 0; nt < 4; nt++) {
            float p0 = __expf(S[nt][0] - mn0);
            float p1 = __expf(S[nt][1] - mn0);
            float p2 = __expf(S[nt][2] - mn1);
            float p3 = __expf(S[nt][3] - mn1);
            S[nt][0] = p0; S[nt][1] = p1; S[nt][2] = p2; S[nt][3] = p3;
            ls0 += p0 + p1; ls1 += p2 + p3;
        }
        ls0 += __shfl_xor_sync(0xffffffffu, ls0, 1);
        ls0 += __shfl_xor_sync(0xffffffffu, ls0, 2);
        ls1 += __shfl_xor_sync(0xffffffffu, ls1, 1);
        ls1 += __shfl_xor_sync(0xffffffffu, ls1, 2);
        l0 = l0 * f0 + ls0;
        l1 = l1 * f1 + ls1;

#pragma unroll
        for (int nt = 0; nt < 16; nt++) {
            O[nt][0] *= f0; O[nt][1] *= f0;
            O[nt][2] *= f1; O[nt][3] *= f1;
        }

#pragma unroll
        for (int ks2 = 0; ks2 < 2; ks2++) {
            uint32_t ahi[4], alo[4];
            split2(S[2 * ks2][0],     S[2 * ks2][1],     ahi[0], alo[0]);
            split2(S[2 * ks2][2],     S[2 * ks2][3],     ahi[1], alo[1]);
            split2(S[2 * ks2 + 1][0], S[2 * ks2 + 1][1], ahi[2], alo[2]);
            split2(S[2 * ks2 + 1][2], S[2 * ks2 + 1][3], ahi[3], alo[3]);
#pragma unroll
            for (int ntp = 0; ntp < 8; ntp++) {
                uint32_t vh4[4], vl4[4];
                ldsm4t(vh4, uVh + offV + ks2 * (16 * LDH * 2) + ntp * 32);
                ldsm4t(vl4, uVl + offV + ks2 * (16 * LDH * 2) + ntp * 32);
                mma16816(O[2 * ntp],     ahi, vh4);
                mma16816(O[2 * ntp + 1], ahi, vh4 + 2);
                mma16816(O[2 * ntp],     ahi, vl4);
                mma16816(O[2 * ntp + 1], ahi, vl4 + 2);
                mma16816(O[2 * ntp],     alo, vh4);
                mma16816(O[2 * ntp + 1], alo, vh4 + 2);
            }
        }
    }

    float inv0 = 1.f / l0, inv1 = 1.f / l1;
    size_t ob0 = (size_t)(qb * 64 + wm * 16 + gid) * HID + (size_t)h * HDIM;
    size_t ob1 = ob0 + 8 * (size_t)HID;
#pragma unroll
    for (int nt = 0; nt < 16; nt++) {
        int col = nt * 8 + tig * 2;
        uint32_t hh, ll;
        split2(O[nt][0] * inv0, O[nt][1] * inv0, hh, ll);
        *(uint32_t*)&ahi_out[ob0 + col] = hh;
        *(uint32_t*)&alo_out[ob0 + col] = ll;
        split2(O[nt][2] * inv1, O[nt][3] * inv1, hh, ll);
        *(uint32_t*)&ahi_out[ob1 + col] = hh;
        *(uint32_t*)&alo_out[ob1 + col] = ll;
    }
}

// =====================================================================
// Host orchestration — multi-stream fork/join (graph-capturable)
// =====================================================================
static void convS(cudaStream_t st, const void* in, __nv_bfloat16* hi,
                  __nv_bfloat16* lo, size_t n) {
    int n4 = (int)(n / 4);
    int blocks = (n4 + 255) / 256;
    if (blocks > 6144) blocks = 6144;
    conv_split<<<blocks, 256, 0, st>>>((const float4*)in, hi, lo, n4);
}

#define SYM(v, s) cudaGetSymbolAddress((void**)&v, s)

extern "C" void kernel_launch(void* const* d_in, const int* in_sizes, int n_in,
                              void* d_out, int out_size)
{
    const float* hs     = (const float*)d_in[0];
    const float* cosp   = (const float*)d_in[1];
    const float* sinp   = (const float*)d_in[2];
    const float* bcos   = (const float*)d_in[3];
    const float* bsin   = (const float*)d_in[4];
    const int*   memidx = (const int*)d_in[5];
    const int*   imidx  = (const int*)d_in[6];
    const float* kc_in  = (const float*)d_in[7];
    const float* vc_in  = (const float*)d_in[8];
    const int*   blkoff = (const int*)d_in[9];
    const float* wqkv_w = (const float*)d_in[10];
    const float* wqkv_A = (const float*)d_in[11];
    const float* wqkv_B = (const float*)d_in[12];
    const float* wqkv_MA= (const float*)d_in[13];
    const float* wqkv_MB= (const float*)d_in[14];
    const float* wo_w   = (const float*)d_in[15];
    const float* wo_A   = (const float*)d_in[16];
    const float* wo_B   = (const float*)d_in[17];
    const float* wo_MA  = (const float*)d_in[18];
    const float* wo_MB  = (const float*)d_in[19];

    float* outp   = (float*)d_out;
    float* kc_out = outp + (size_t)TT * HID;
    float* vc_out = kc_out + CACHE_ELEMS;

    float *qkv;
    SYM(qkv, g_qkv);

    __nv_bfloat16 *hs_hi,*hs_lo,*attn_hi,*attn_lo,*q_hi,*q_lo,*k_hi,*k_lo,*v_hi,*v_lo;
    __nv_bfloat16 *tim_hi,*tim_lo,*tmem_hi,*tmem_lo;
    __nv_bfloat16 *wqkv_hi,*wqkv_lo,*wqA_hi,*wqA_lo,*wqB_hi,*wqB_lo,*wqMA_hi,*wqMA_lo,*wqMB_hi,*wqMB_lo;
    __nv_bfloat16 *wo_hi,*wo_lo,*woA_hi,*woA_lo,*woB_hi,*woB_lo,*woMA_hi,*woMA_lo,*woMB_hi,*woMB_lo;
    SYM(hs_hi, g_hs_hi);     SYM(hs_lo, g_hs_lo);
    SYM(attn_hi, g_attn_hi); SYM(attn_lo, g_attn_lo);
    SYM(q_hi, g_q_hi);       SYM(q_lo, g_q_lo);
    SYM(k_hi, g_k_hi);       SYM(k_lo, g_k_lo);
    SYM(v_hi, g_v_hi);       SYM(v_lo, g_v_lo);
    SYM(tim_hi, g_tim_hi);   SYM(tim_lo, g_tim_lo);
    SYM(tmem_hi, g_tmem_hi); SYM(tmem_lo, g_tmem_lo);
    SYM(wqkv_hi, g_wqkv_hi); SYM(wqkv_lo, g_wqkv_lo);
    SYM(wqA_hi, g_wqA_hi);   SYM(wqA_lo, g_wqA_lo);
    SYM(wqB_hi, g_wqB_hi);   SYM(wqB_lo, g_wqB_lo);
    SYM(wqMA_hi, g_wqMA_hi); SYM(wqMA_lo, g_wqMA_lo);
    SYM(wqMB_hi, g_wqMB_hi); SYM(wqMB_lo, g_wqMB_lo);
    SYM(wo_hi, g_wo_hi);     SYM(wo_lo, g_wo_lo);
    SYM(woA_hi, g_woA_hi);   SYM(woA_lo, g_woA_lo);
    SYM(woB_hi, g_woB_hi);   SYM(woB_lo, g_woB_lo);
    SYM(woMA_hi, g_woMA_hi); SYM(woMA_lo, g_woMA_lo);
    SYM(woMB_hi, g_woMB_hi); SYM(woMB_lo, g_woMB_lo);

    cudaFuncSetAttribute(gemm_hl, cudaFuncAttributeMaxDynamicSharedMemorySize, GEMM_SMEM);
    cudaFuncSetAttribute(flash_mma, cudaFuncAttributeMaxDynamicSharedMemorySize, FA3_SMEM);

    cudaStream_t s1, s2;
    cudaStreamCreateWithFlags(&s1, cudaStreamNonBlocking);
    cudaStreamCreateWithFlags(&s2, cudaStreamNonBlocking);
    cudaEvent_t eFork, eHs, eWqA, eWqB, eQKV, eCpy, eWoC, eLA, eLbM, eQall,
                eFlash, eWoA, eWOm, eS1, eS2;
    cudaEvent_t* evs[15] = {&eFork,&eHs,&eWqA,&eWqB,&eQKV,&eCpy,&eWoC,&eLA,&eLbM,
                            &eQall,&eFlash,&eWoA,&eWOm,&eS1,&eS2};
    for (int i = 0; i < 15; i++) cudaEventCreateWithFlags(evs[i], cudaEventDisableTiming);

    // ---- fork immediately: conversions run concurrently ----
    cudaEventRecord(eFork, 0);
    cudaStreamWaitEvent(s1, eFork, 0);
    cudaStreamWaitEvent(s2, eFork, 0);

    // origin: the big weight conversion (critical path for QKV gemm)
    convS(0, wqkv_w, wqkv_hi, wqkv_lo, (size_t)QKVO * HID);

    // s1: hs + LoRA-A/B weights concurrently with wqkv conv
    convS(s1, hs, hs_hi, hs_lo, (size_t)TT * HID);
    cudaEventRecord(eHs, s1);
    convS(s1, wqkv_A, wqA_hi, wqA_lo, (size_t)RANK * HID);
    convS(s1, wqkv_MA, wqMA_hi, wqMA_lo, (size_t)RANK * HID);
    cudaEventRecord(eWqA, s1);
    convS(s1, wqkv_B, wqB_hi, wqB_lo, (size_t)QKVO * RANK);
    convS(s1, wqkv_MB, wqMB_hi, wqMB_lo, (size_t)QKVO * RANK);
    cudaEventRecord(eWqB, s1);

    // origin: QKV main projection
    cudaStreamWaitEvent(0, eHs, 0);
    gemm_hl<<<dim3(QKVO/128, TT/128), 256, GEMM_SMEM>>>(hs_hi, hs_lo, wqkv_hi, wqkv_lo,
        qkv, nullptr, nullptr, TT, QKVO, HID, nullptr, nullptr);
    cudaEventRecord(eQKV, 0);

    // s1: cache memcpys + WO-side conversions
    cudaMemcpyAsync(kc_out, kc_in, (size_t)CACHE_ELEMS * sizeof(float),
                    cudaMemcpyDeviceToDevice, s1);
    cudaMemcpyAsync(vc_out, vc_in, (size_t)CACHE_ELEMS * sizeof(float),
                    cudaMemcpyDeviceToDevice, s1);
    cudaEventRecord(eCpy, s1);
    convS(s1, wo_w, wo_hi, wo_lo, (size_t)HID * HID);
    convS(s1, wo_A, woA_hi, woA_lo, (size_t)RANK * HID);
    convS(s1, wo_MA, woMA_hi, woMA_lo, (size_t)RANK * HID);
    convS(s1, wo_B, woB_hi, woB_lo, (size_t)HID * RANK);
    convS(s1, wo_MB, woMB_hi, woMB_lo, (size_t)HID * RANK);
    cudaEventRecord(eWoC, s1);

    // ---- s2: QKV LoRA-A (both), record eLA ----
    cudaStreamWaitEvent(s2, eWqA, 0);
    gemm_hl<<<dim3(RANK/128, NIM/128), 256, GEMM_SMEM, s2>>>(hs_hi, hs_lo, wqA_hi, wqA_lo,
        nullptr, tim_hi, tim_lo, NIM, RANK, HID, imidx, nullptr);
    gemm_hl<<<dim3(RANK/128, NMEM/128), 256, GEMM_SMEM, s2>>>(hs_hi, hs_lo, wqMA_hi, wqMA_lo,
        nullptr, tmem_hi, tmem_lo, NMEM, RANK, HID, memidx, nullptr);
    cudaEventRecord(eLA, s2);

    // ---- QKV LoRA-B concurrently: im on s2, mem on s1 ----
    cudaStreamWaitEvent(s2, eQKV, 0);
    cudaStreamWaitEvent(s2, eWqB, 0);
    gemm_hl<<<dim3(QKVO/128, NIM/128), 256, GEMM_SMEM, s2>>>(tim_hi, tim_lo, wqB_hi, wqB_lo,
        qkv, nullptr, nullptr, NIM, QKVO, RANK, nullptr, imidx);

    cudaStreamWaitEvent(s1, eLA, 0);
    cudaStreamWaitEvent(s1, eQKV, 0);
    gemm_hl<<<dim3(QKVO/128, NMEM/128), 256, GEMM_SMEM, s1>>>(tmem_hi, tmem_lo, wqMB_hi, wqMB_lo,
        qkv, nullptr, nullptr, NMEM, QKVO, RANK, nullptr, memidx);
    cudaEventRecord(eLbM, s1);
    cudaEventRecord(eS1, s1);

    // ---- s2: cache fill + rope (need both LoRA-B writers + memcpys) ----
    cudaStreamWaitEvent(s2, eLbM, 0);
    cudaStreamWaitEvent(s2, eCpy, 0);
    fill_cache_kernel<<<NMEM, dim3(64, 8), 0, s2>>>(qkv, memidx, blkoff, bcos, bsin, kc_out, vc_out);
    rope_convert<<<dim3(TT, 12), dim3(32, 4), 0, s2>>>(qkv, cosp, sinp, q_hi, q_lo, k_hi, k_lo, v_hi, v_lo);
    cudaEventRecord(eQall, s2);

    // ---- origin: flash attention (single launch, heavy-first) ----
    cudaStreamWaitEvent(0, eQall, 0);
    flash_mma<<<dim3(TT/64, NHEADS), 128, FA3_SMEM>>>(q_hi, q_lo, k_hi, k_lo,
        v_hi, v_lo, attn_hi, attn_lo);
    cudaEventRecord(eFlash, 0);

    // ---- s2: WO LoRA-A (both, overlaps WO main); later WO LoRA-B mem ----
    cudaStreamWaitEvent(s2, eFlash, 0);
    cudaStreamWaitEvent(s2, eWoC, 0);
    gemm_hl<<<dim3(RANK/128, NIM/128), 256, GEMM_SMEM, s2>>>(attn_hi, attn_lo, woA_hi, woA_lo,
        nullptr, tim_hi, tim_lo, NIM, RANK, HID, imidx, nullptr);
    gemm_hl<<<dim3(RANK/128, NMEM/128), 256, GEMM_SMEM, s2>>>(attn_hi, attn_lo, woMA_hi, woMA_lo,
        nullptr, tmem_hi, tmem_lo, NMEM, RANK, HID, memidx, nullptr);
    cudaEventRecord(eWoA, s2);

    // ---- origin: WO main projection ----
    cudaStreamWaitEvent(0, eWoC, 0);
    gemm_hl<<<dim3(HID/128, TT/128), 256, GEMM_SMEM>>>(attn_hi, attn_lo, wo_hi, wo_lo,
        outp, nullptr, nullptr, TT, HID, HID, nullptr, nullptr);
    cudaEventRecord(eWOm, 0);

    // ---- WO LoRA-B concurrently: im on s0, mem on s2 ----
    cudaStreamWaitEvent(0, eWoA, 0);
    gemm_hl<<<dim3(HID/128, NIM/128), 256, GEMM_SMEM>>>(tim_hi, tim_lo, woB_hi, woB_lo,
        outp, nullptr, nullptr, NIM, HID, RANK, nullptr, imidx);

    cudaStreamWaitEvent(s2, eWOm, 0);
    gemm_hl<<<dim3(HID/128, NMEM/128), 256, GEMM_SMEM, s2>>>(tmem_hi, tmem_lo, woMB_hi, woMB_lo,
        outp, nullptr, nullptr, NMEM, HID, RANK, nullptr, memidx);
    cudaEventRecord(eS2, s2);

    // ---- join forked streams back into origin ----
    cudaStreamWaitEvent(0, eS1, 0);
    cudaStreamWaitEvent(0, eS2, 0);

    cudaStreamCaptureStatus st = cudaStreamCaptureStatusNone;
    cudaStreamIsCapturing(0, &st);
    if (st == cudaStreamCaptureStatusNone) {
        for (int i = 0; i < 15; i++) cudaEventDestroy(*evs[i]);
        cudaStreamDestroy(s1);
        cudaStreamDestroy(s2);
    }
}

// round 17
// speedup vs baseline: 1.1095x; 1.0082x over previous
#include <cuda_runtime.h>
#include <cuda_bf16.h>
#include <math.h>
#include <float.h>
#include <stdint.h>

#define TT     2048
#define HID    4096
#define NHEADS 32
#define NKVH   8
#define HDIM   128
#define QKVO   6144
#define RANK   256
#define NIM    512
#define NMEM   128
#define CACHE_ELEMS (4*64*NKVH*HDIM)

// ---------------- scratch ----------------
__device__ float g_qkv[TT * QKVO];

__device__ __nv_bfloat16 g_hs_hi[TT*HID],    g_hs_lo[TT*HID];
__device__ __nv_bfloat16 g_attn_hi[TT*HID],  g_attn_lo[TT*HID];
__device__ __nv_bfloat16 g_q_hi[TT*HID],     g_q_lo[TT*HID];
__device__ __nv_bfloat16 g_k_hi[TT*NKVH*HDIM], g_k_lo[TT*NKVH*HDIM];
__device__ __nv_bfloat16 g_v_hi[TT*NKVH*HDIM], g_v_lo[TT*NKVH*HDIM];
__device__ __nv_bfloat16 g_tim_hi[NIM*RANK],  g_tim_lo[NIM*RANK];
__device__ __nv_bfloat16 g_tmem_hi[NMEM*RANK], g_tmem_lo[NMEM*RANK];

__device__ __nv_bfloat16 g_wqkv_hi[QKVO*HID], g_wqkv_lo[QKVO*HID];
__device__ __nv_bfloat16 g_wqA_hi[RANK*HID],  g_wqA_lo[RANK*HID];
__device__ __nv_bfloat16 g_wqB_hi[QKVO*RANK], g_wqB_lo[QKVO*RANK];
__device__ __nv_bfloat16 g_wqMA_hi[RANK*HID], g_wqMA_lo[RANK*HID];
__device__ __nv_bfloat16 g_wqMB_hi[QKVO*RANK],g_wqMB_lo[QKVO*RANK];
__device__ __nv_bfloat16 g_wo_hi[HID*HID],    g_wo_lo[HID*HID];
__device__ __nv_bfloat16 g_woA_hi[RANK*HID],  g_woA_lo[RANK*HID];
__device__ __nv_bfloat16 g_woB_hi[HID*RANK],  g_woB_lo[HID*RANK];
__device__ __nv_bfloat16 g_woMA_hi[RANK*HID], g_woMA_lo[RANK*HID];
__device__ __nv_bfloat16 g_woMB_hi[HID*RANK], g_woMB_lo[HID*RANK];

// ---------------- helpers ----------------
__device__ __forceinline__ uint32_t pack_bf16(float x, float y) {
    __nv_bfloat162 t = __floats2bfloat162_rn(x, y);
    return *reinterpret_cast<uint32_t*>(&t);
}
__device__ __forceinline__ void split2(float x, float y, uint32_t& h, uint32_t& l) {
    float hx = __bfloat162float(__float2bfloat16(x));
    float hy = __bfloat162float(__float2bfloat16(y));
    h = pack_bf16(x, y);
    l = pack_bf16(x - hx, y - hy);
}
__device__ __forceinline__ void mma16816(float* c, const uint32_t* a, const uint32_t* b) {
    asm volatile(
        "mma.sync.aligned.m16n8k16.row.col.f32.bf16.bf16.f32 "
        "{%0,%1,%2,%3}, {%4,%5,%6,%7}, {%8,%9}, {%0,%1,%2,%3};\n"
        : "+f"(c[0]), "+f"(c[1]), "+f"(c[2]), "+f"(c[3])
        : "r"(a[0]), "r"(a[1]), "r"(a[2]), "r"(a[3]), "r"(b[0]), "r"(b[1]));
}
__device__ __forceinline__ uint32_t s2u(const void* p) {
    return (uint32_t)__cvta_generic_to_shared(p);
}
__device__ __forceinline__ void cp16(uint32_t saddr, const void* gaddr) {
    asm volatile("cp.async.cg.shared.global [%0], [%1], 16;\n" :: "r"(saddr), "l"(gaddr));
}
#define CP_COMMIT() asm volatile("cp.async.commit_group;\n")
#define CP_WAIT0()  asm volatile("cp.async.wait_group 0;\n")
__device__ __forceinline__ void ldsm4(uint32_t* r, uint32_t saddr) {
    asm volatile("ldmatrix.sync.aligned.m8n8.x4.shared.b16 {%0,%1,%2,%3}, [%4];\n"
        : "=r"(r[0]), "=r"(r[1]), "=r"(r[2]), "=r"(r[3]) : "r"(saddr));
}
__device__ __forceinline__ void ldsm4t(uint32_t* r, uint32_t saddr) {
    asm volatile("ldmatrix.sync.aligned.m8n8.x4.trans.shared.b16 {%0,%1,%2,%3}, [%4];\n"
        : "=r"(r[0]), "=r"(r[1]), "=r"(r[2]), "=r"(r[3]) : "r"(saddr));
}

// ---------------- split conversion (8 floats/thread, 16B stores) ----------------
__global__ void conv_split(const float4* __restrict__ in,
                           __nv_bfloat16* __restrict__ hi,
                           __nv_bfloat16* __restrict__ lo, int n8)
{
    int i = blockIdx.x * blockDim.x + threadIdx.x;
    int stride = gridDim.x * blockDim.x;
    for (; i < n8; i += stride) {
        float4 a = in[2 * i];
        float4 b = in[2 * i + 1];
        uint32_t h[4], l[4];
        split2(a.x, a.y, h[0], l[0]);
        split2(a.z, a.w, h[1], l[1]);
        split2(b.x, b.y, h[2], l[2]);
        split2(b.z, b.w, h[3], l[3]);
        *(uint4*)&hi[8 * i] = make_uint4(h[0], h[1], h[2], h[3]);
        *(uint4*)&lo[8 * i] = make_uint4(l[0], l[1], l[2], l[3]);
    }
}

// fused RoPE + hi/lo split: reads RAW qkv f32 (does NOT modify it)
// grid (TT, 12), block (32, 4)
__global__ void rope_convert(const float* __restrict__ qkv,
    const float* __restrict__ cosp, const float* __restrict__ sinp,
    __nv_bfloat16* __restrict__ qh, __nv_bfloat16* __restrict__ ql,
    __nv_bfloat16* __restrict__ kh, __nv_bfloat16* __restrict__ kl,
    __nv_bfloat16* __restrict__ vh, __nv_bfloat16* __restrict__ vl)
{
    int t = blockIdx.x;
    int hh = blockIdx.y * 4 + threadIdx.y;
    int d4 = threadIdx.x * 4;
    int srcoff;
    __nv_bfloat16 *dh, *dl;
    size_t dst;
    bool dorope = true;
    if (hh < 32) {
        srcoff = (hh >> 2) * 768 + (hh & 3) * 128;
        dh = qh; dl = ql;
        dst = ((size_t)t * 32 + hh) * 128 + d4;
    } else if (hh < 40) {
        srcoff = (hh - 32) * 768 + 512;
        dh = kh; dl = kl;
        dst = ((size_t)t * 8 + (hh - 32)) * 128 + d4;
    } else {
        srcoff = (hh - 40) * 768 + 640;
        dh = vh; dl = vl;
        dst = ((size_t)t * 8 + (hh - 40)) * 128 + d4;
        dorope = false;
    }
    const float* src = qkv + (size_t)t * QKVO + srcoff;
    float o[4];
    if (dorope) {
        const float* c = cosp + (size_t)t * HDIM;
        const float* s = sinp + (size_t)t * HDIM;
        float4 x  = *(const float4*)(src + d4);
        int p4 = (d4 < 64) ? d4 + 64 : d4 - 64;
        float4 xp = *(const float4*)(src + p4);
        float sg = (d4 < 64) ? -1.f : 1.f;
        o[0] = x.x * c[d4+0] + sg * xp.x * s[d4+0];
        o[1] = x.y * c[d4+1] + sg * xp.y * s[d4+1];
        o[2] = x.z * c[d4+2] + sg * xp.z * s[d4+2];
        o[3] = x.w * c[d4+3] + sg * xp.w * s[d4+3];
    } else {
        float4 x = *(const float4*)(src + d4);
        o[0] = x.x; o[1] = x.y; o[2] = x.z; o[3] = x.w;
    }
    uint32_t h0, l0, h1, l1;
    split2(o[0], o[1], h0, l0);
    split2(o[2], o[3], h1, l1);
    *(uint32_t*)&dh[dst]     = h0;
    *(uint32_t*)&dh[dst + 2] = h1;
    *(uint32_t*)&dl[dst]     = l0;
    *(uint32_t*)&dl[dst + 2] = l1;
}

// =====================================================================
// Pipelined hi/lo GEMM — 2-stage, 2 CTAs/SM, L2 swizzle
// =====================================================================
#define LDKS 40
#define GTS (128 * LDKS)
#define GSTAGE (4 * GTS * 2)
#define GEMM_SMEM (2 * GSTAGE)

__global__ __launch_bounds__(256, 2) void gemm_hl(
    const __nv_bfloat16* __restrict__ Ahi, const __nv_bfloat16* __restrict__ Alo,
    const __nv_bfloat16* __restrict__ Bhi, const __nv_bfloat16* __restrict__ Blo,
    float* __restrict__ C, __nv_bfloat16* __restrict__ Chi, __nv_bfloat16* __restrict__ Clo,
    int M, int N, int K, const int* __restrict__ gatherA,
    const int* __restrict__ scatterC)
{
    extern __shared__ __nv_bfloat16 smg[];
    uint32_t usm = s2u(smg);

    int tid = threadIdx.x;
    int bm, bn;
    {
        int G = (gridDim.x < 8) ? gridDim.x : 8;
        if (gridDim.x % G) { bn = blockIdx.x; bm = blockIdx.y; }
        else {
            int idb = blockIdx.y * gridDim.x + blockIdx.x;
            int gsz = G * gridDim.y;
            int grp = idb / gsz;
            int rem = idb - grp * gsz;
            bn = grp * G + rem % G;
            bm = rem / G;
        }
    }
    int warp = tid >> 5, lane = tid & 31;
    int wm = warp & 1, wn = warp >> 1;
    int gid = lane >> 2, tig = lane & 3;
    int mi = lane >> 3, lr = lane & 7;

    size_t aoff[2], boff[2];
    uint32_t soffB[2];
#pragma unroll
    for (int i = 0; i < 2; i++) {
        int idx = tid + 256 * i;
        int r = idx >> 2;
        int c8 = (idx & 3) * 8;
        int ar = bm * 128 + r;
        if (gatherA) ar = __ldg(&gatherA[ar]);
        aoff[i] = (size_t)ar * K + c8;
        boff[i] = (size_t)(bn * 128 + r) * K + c8;
        soffB[i] = (uint32_t)(r * LDKS + c8) * 2;
    }

    uint32_t offA = (uint32_t)((wm * 64 + (mi & 1) * 8 + lr) * LDKS + (mi >> 1) * 8) * 2;
    uint32_t offB = (uint32_t)((wn * 32 + (mi >> 1) * 8 + lr) * LDKS + (mi & 1) * 8) * 2;

    float acc[4][4][4];
#pragma unroll
    for (int mt = 0; mt < 4; mt++)
#pragma unroll
        for (int nt = 0; nt < 4; nt++)
#pragma unroll
            for (int e = 0; e < 4; e++) acc[mt][nt][e] = 0.f;

    int nk = K / 32;

#define G_ISSUE(s, k0)                                                     \
    {                                                                      \
        uint32_t sb = usm + (uint32_t)(s) * GSTAGE;                        \
        _Pragma("unroll")                                                  \
        for (int i = 0; i < 2; i++) {                                      \
            cp16(sb + soffB[i],             Ahi + aoff[i] + (k0));         \
            cp16(sb + GTS*2 + soffB[i],     Alo + aoff[i] + (k0));         \
            cp16(sb + 2*GTS*2 + soffB[i],   Bhi + boff[i] + (k0));         \
            cp16(sb + 3*GTS*2 + soffB[i],   Blo + boff[i] + (k0));         \
        }                                                                  \
    }

    G_ISSUE(0, 0); CP_COMMIT();

    for (int t = 0; t < nk; t++) {
        CP_WAIT0();
        __syncthreads();
        if (t + 1 < nk) { G_ISSUE((t + 1) & 1, (t + 1) * 32); CP_COMMIT(); }

        uint32_t sb = usm + (uint32_t)(t & 1) * GSTAGE;
        uint32_t uAh = sb, uAl = sb + GTS * 2;
        uint32_t uBh = sb + 2 * GTS * 2, uBl = sb + 3 * GTS * 2;

#pragma unroll
        for (int kb = 0; kb < 64; kb += 32) {
            uint32_t ah[4][4], al[4][4];
            uint32_t bh[2][4], bl[2][4];
#pragma unroll
            for (int mt = 0; mt < 4; mt++) {
                ldsm4(ah[mt], uAh + offA + mt * (16 * LDKS * 2) + kb);
                ldsm4(al[mt], uAl + offA + mt * (16 * LDKS * 2) + kb);
            }
#pragma unroll
            for (int nn = 0; nn < 2; nn++) {
                ldsm4(bh[nn], uBh + offB + nn * (16 * LDKS * 2) + kb);
                ldsm4(bl[nn], uBl + offB + nn * (16 * LDKS * 2) + kb);
            }
#pragma unroll
            for (int nt = 0; nt < 4; nt++) {
                const uint32_t* bf = bh[nt >> 1] + (nt & 1) * 2;
#pragma unroll
                for (int mt = 0; mt < 4; mt++)
                    mma16816(acc[mt][nt], ah[mt], bf);
            }
#pragma unroll
            for (int nt = 0; nt < 4; nt++) {
                const uint32_t* bf = bl[nt >> 1] + (nt & 1) * 2;
#pragma unroll
                for (int mt = 0; mt < 4; mt++)
                    mma16816(acc[mt][nt], ah[mt], bf);
            }
#pragma unroll
            for (int nt = 0; nt < 4; nt++) {
                const uint32_t* bf = bh[nt >> 1] + (nt & 1) * 2;
#pragma unroll
                for (int mt = 0; mt < 4; mt++)
                    mma16816(acc[mt][nt], al[mt], bf);
            }
        }
    }

    if (scatterC) {
#pragma unroll
        for (int mt = 0; mt < 4; mt++) {
            int r0 = bm * 128 + wm * 64 + mt * 16 + gid;
            int rr0 = __ldg(&scatterC[r0]);
            int rr1 = __ldg(&scatterC[r0 + 8]);
#pragma unroll
            for (int nt = 0; nt < 4; nt++) {
                int c0 = bn * 128 + wn * 32 + nt * 8 + tig * 2;
                atomicAdd(&C[(size_t)rr0 * N + c0],     acc[mt][nt][0]);
                atomicAdd(&C[(size_t)rr0 * N + c0 + 1], acc[mt][nt][1]);
                atomicAdd(&C[(size_t)rr1 * N + c0],     acc[mt][nt][2]);
                atomicAdd(&C[(size_t)rr1 * N + c0 + 1], acc[mt][nt][3]);
            }
        }
    } else if (C) {
#pragma unroll
        for (int mt = 0; mt < 4; mt++) {
            int r0 = bm * 128 + wm * 64 + mt * 16 + gid;
#pragma unroll
            for (int nt = 0; nt < 4; nt++) {
                int c0 = bn * 128 + wn * 32 + nt * 8 + tig * 2;
                *(float2*)&C[(size_t)r0 * N + c0] =
                    make_float2(acc[mt][nt][0], acc[mt][nt][1]);
                *(float2*)&C[(size_t)(r0 + 8) * N + c0] =
                    make_float2(acc[mt][nt][2], acc[mt][nt][3]);
            }
        }
    } else {
#pragma unroll
        for (int mt = 0; mt < 4; mt++) {
            int r0 = bm * 128 + wm * 64 + mt * 16 + gid;
#pragma unroll
            for (int nt = 0; nt < 4; nt++) {
                int c0 = bn * 128 + wn * 32 + nt * 8 + tig * 2;
                uint32_t h, l;
                split2(acc[mt][nt][0], acc[mt][nt][1], h, l);
                *(uint32_t*)&Chi[(size_t)r0 * N + c0] = h;
                *(uint32_t*)&Clo[(size_t)r0 * N + c0] = l;
                split2(acc[mt][nt][2], acc[mt][nt][3], h, l);
                *(uint32_t*)&Chi[(size_t)(r0 + 8) * N + c0] = h;
                *(uint32_t*)&Clo[(size_t)(r0 + 8) * N + c0] = l;
            }
        }
    }
}

// ---------------- KV-cache fill (reads qkv incl. LoRA) ----------------
__global__ void fill_cache_kernel(const float* __restrict__ qkv,
                                  const int* __restrict__ mem_idx,
                                  const int* __restrict__ blkoff,
                                  const float* __restrict__ bcos,
                                  const float* __restrict__ bsin,
                                  float* __restrict__ kc, float* __restrict__ vc)
{
    int m = blockIdx.x;
    int h = threadIdx.y;
    int d = threadIdx.x;
    int tok = mem_idx[m];
    int blk = blkoff[m >> 6];
    int off = m & 63;
    const float* kb = qkv + (size_t)tok * QKVO + (size_t)(h * 6 + 4) * HDIM;
    const float* vb = qkv + (size_t)tok * QKVO + (size_t)(h * 6 + 5) * HDIM;
    size_t dsti = (((size_t)(blk * 64 + off)) * NKVH + h) * HDIM;
    const float* c = bcos + (size_t)m * HDIM;
    const float* s = bsin + (size_t)m * HDIM;
    float x1 = kb[d], x2 = kb[d + 64];
    kc[dsti + d]      = x1 * c[d]      - x2 * s[d];
    kc[dsti + d + 64] = x2 * c[d + 64] + x1 * s[d + 64];
    vc[dsti + d]      = vb[d];
    vc[dsti + d + 64] = vb[d + 64];
}

// =====================================================================
// Flash attention (mma.sync), causal, GQA 4:1.
// BM=64 (4 warps), KV tile 32, 2 CTAs/SM. Heavy q-blocks first.
// =====================================================================
#define LDH  136
#define FQ64 (64 * LDH)
#define FT32 (32 * LDH)
#define FA3_SMEM ((2 * FQ64 + 2 * 4 * FT32) * 2)

__global__ __launch_bounds__(128, 2) void flash_mma(
    const __nv_bfloat16* __restrict__ qhi, const __nv_bfloat16* __restrict__ qlo,
    const __nv_bfloat16* __restrict__ khi, const __nv_bfloat16* __restrict__ klo,
    const __nv_bfloat16* __restrict__ vhi, const __nv_bfloat16* __restrict__ vlo,
    __nv_bfloat16* __restrict__ ahi_out, __nv_bfloat16* __restrict__ alo_out)
{
    extern __shared__ __nv_bfloat16 smf[];
    uint32_t usm = s2u(smf);
    __nv_bfloat16* Qh = smf;
    __nv_bfloat16* Ql = smf + FQ64;

    int tid = threadIdx.x;
    int wm = tid >> 5, lane = tid & 31;
    int gid = lane >> 2, tig = lane & 3;
    int qb = (gridDim.x - 1) - blockIdx.x;
    int h = blockIdx.y;
    int kvh = h >> 2;

#pragma unroll
    for (int i = 0; i < 8; i++) {
        int idx = tid + 128 * i;
        int r = idx >> 4, c8 = (idx & 15) * 8;
        size_t src = ((size_t)(qb * 64 + r) * 32 + h) * 128 + c8;
        *(uint4*)&Qh[r * LDH + c8] = *(const uint4*)&qhi[src];
        *(uint4*)&Ql[r * LDH + c8] = *(const uint4*)&qlo[src];
    }

    uint32_t kv_goff[4], kv_soff[4];
#pragma unroll
    for (int i = 0; i < 4; i++) {
        int idx = tid + 128 * i;
        int r = idx >> 4, c8 = (idx & 15) * 8;
        kv_goff[i] = (uint32_t)(r * (NKVH * HDIM) + kvh * HDIM + c8);
        kv_soff[i] = (uint32_t)(r * LDH + c8) * 2;
    }

    int nkb = 2 * (qb + 1);

#define F_ISSUE(kb, s)                                                        \
    {                                                                         \
        uint32_t sb = usm + (2 * FQ64 + (s) * 4 * FT32) * 2;                  \
        size_t tb = (size_t)(kb) * 32 * (NKVH * HDIM);                        \
        _Pragma("unroll")                                                     \
        for (int i = 0; i < 4; i++) {                                         \
            cp16(sb + kv_soff[i],            khi + tb + kv_goff[i]);          \
            cp16(sb + FT32*2 + kv_soff[i],   klo + tb + kv_goff[i]);          \
            cp16(sb + 2*FT32*2 + kv_soff[i], vhi + tb + kv_goff[i]);          \
            cp16(sb + 3*FT32*2 + kv_soff[i], vlo + tb + kv_goff[i]);          \
        }                                                                     \
    }

    F_ISSUE(0, 0); CP_COMMIT();

    int mi = lane >> 3, lr = lane & 7;
    uint32_t offQ = (uint32_t)((16 * wm + (mi & 1) * 8 + lr) * LDH + (mi >> 1) * 8) * 2;
    uint32_t offK = (uint32_t)(((mi >> 1) * 8 + lr) * LDH + (mi & 1) * 8) * 2;
    uint32_t offV = (uint32_t)(((mi & 1) * 8 + lr) * LDH + (mi >> 1) * 8) * 2;
    uint32_t uQh = usm, uQl = usm + FQ64 * 2;

    float O[16][4];
#pragma unroll
    for (int nt = 0; nt < 16; nt++)
#pragma unroll
        for (int e = 0; e < 4; e++) O[nt][e] = 0.f;

    float m0 = -1e30f, m1 = -1e30f, l0 = 0.f, l1 = 0.f;
    int qg0 = qb * 64 + wm * 16 + gid;
    int qg1 = qg0 + 8;
    const float scale = 0.08838834764831845f;

    for (int kb = 0; kb < nkb; kb++) {
        CP_WAIT0();
        __syncthreads();
        if (kb + 1 < nkb) { F_ISSUE(kb + 1, (kb + 1) & 1); CP_COMMIT(); }

        uint32_t sb = usm + (2 * FQ64 + (kb & 1) * 4 * FT32) * 2;
        uint32_t uKh = sb, uKl = sb + FT32 * 2;
        uint32_t uVh = sb + 2 * FT32 * 2, uVl = sb + 3 * FT32 * 2;

        float S[4][4];
#pragma unroll
        for (int nt = 0; nt < 4; nt++)
#pragma unroll
            for (int e = 0; e < 4; e++) S[nt][e] = 0.f;

#pragma unroll
        for (int ks = 0; ks < 8; ks++) {
            uint32_t qh4[4], ql4[4];
            ldsm4(qh4, uQh + offQ + ks * 32);
            ldsm4(ql4, uQl + offQ + ks * 32);
#pragma unroll
            for (int ntp = 0; ntp < 2; ntp++) {
                uint32_t kh4[4], kl4[4];
                ldsm4(kh4, uKh + offK + ntp * (16 * LDH * 2) + ks * 32);
                ldsm4(kl4, uKl + offK + ntp * (16 * LDH * 2) + ks * 32);
                mma16816(S[2 * ntp],     qh4, kh4);
                mma16816(S[2 * ntp + 1], qh4, kh4 + 2);
                mma16816(S[2 * ntp],     qh4, kl4);
                mma16816(S[2 * ntp + 1], qh4, kl4 + 2);
                mma16816(S[2 * ntp],     ql4, kh4);
                mma16816(S[2 * ntp + 1], ql4, kh4 + 2);
            }
        }

        int kvb = kb * 32;
        float rmax0 = -1e30f, rmax1 = -1e30f;
#pragma unroll
        for (int nt = 0; nt < 4; nt++) {
            int kg = kvb + nt * 8 + tig * 2;
            float s0 = (kg     <= qg0) ? S[nt][0] * scale : -1e30f;
            float s1 = (kg + 1 <= qg0) ? S[nt][1] * scale : -1e30f;
            float s2 = (kg     <= qg1) ? S[nt][2] * scale : -1e30f;
            float s3 = (kg + 1 <= qg1) ? S[nt][3] * scale : -1e30f;
            S[nt][0] = s0; S[nt][1] = s1; S[nt][2] = s2; S[nt][3] = s3;
            rmax0 = fmaxf(rmax0, fmaxf(s0, s1));
            rmax1 = fmaxf(rmax1, fmaxf(s2, s3));
        }
        rmax0 = fmaxf(rmax0, __shfl_xor_sync(0xffffffffu, rmax0, 1));
        rmax0 = fmaxf(rmax0, __shfl_xor_sync(0xffffffffu, rmax0, 2));
        rmax1 = fmaxf(rmax1, __shfl_xor_sync(0xffffffffu, rmax1, 1));
        rmax1 = fmaxf(rmax1, __shfl_xor_sync(0xffffffffu, rmax1, 2));

        float mn0 = fmaxf(m0, rmax0), mn1 = fmaxf(m1, rmax1);
        float f0 = __expf(m0 - mn0), f1 = __expf(m1 - mn1);
        m0 = mn0; m1 = mn1;

        float ls0 = 0.f, ls1 = 0.f;
#pragma unroll
        for (int nt = 0; nt < 4; nt++) {
            float p0 = __expf(S[nt][0] - mn0);
            float p1 = __expf(S[nt][1] - mn0);
            float p2 = __expf(S[nt][2] - mn1);
            float p3 = __expf(S[nt][3] - mn1);
            S[nt][0] = p0; S[nt][1] = p1; S[nt][2] = p2; S[nt][3] = p3;
            ls0 += p0 + p1; ls1 += p2 + p3;
        }
        ls0 += __shfl_xor_sync(0xffffffffu, ls0, 1);
        ls0 += __shfl_xor_sync(0xffffffffu, ls0, 2);
        ls1 += __shfl_xor_sync(0xffffffffu, ls1, 1);
        ls1 += __shfl_xor_sync(0xffffffffu, ls1, 2);
        l0 = l0 * f0 + ls0;
        l1 = l1 * f1 + ls1;

#pragma unroll
        for (int nt = 0; nt < 16; nt++) {
            O[nt][0] *= f0; O[nt][1] *= f0;
            O[nt][2] *= f1; O[nt][3] *= f1;
        }

#pragma unroll
        for (int ks2 = 0; ks2 < 2; ks2++) {
            uint32_t ahi[4], alo[4];
            split2(S[2 * ks2][0],     S[2 * ks2][1],     ahi[0], alo[0]);
            split2(S[2 * ks2][2],     S[2 * ks2][3],     ahi[1], alo[1]);
            split2(S[2 * ks2 + 1][0], S[2 * ks2 + 1][1], ahi[2], alo[2]);
            split2(S[2 * ks2 + 1][2], S[2 * ks2 + 1][3], ahi[3], alo[3]);
#pragma unroll
            for (int ntp = 0; ntp < 8; ntp++) {
                uint32_t vh4[4], vl4[4];
                ldsm4t(vh4, uVh + offV + ks2 * (16 * LDH * 2) + ntp * 32);
                ldsm4t(vl4, uVl + offV + ks2 * (16 * LDH * 2) + ntp * 32);
                mma16816(O[2 * ntp],     ahi, vh4);
                mma16816(O[2 * ntp + 1], ahi, vh4 + 2);
                mma16816(O[2 * ntp],     ahi, vl4);
                mma16816(O[2 * ntp + 1], ahi, vl4 + 2);
                mma16816(O[2 * ntp],     alo, vh4);
                mma16816(O[2 * ntp + 1], alo, vh4 + 2);
            }
        }
    }

    float inv0 = 1.f / l0, inv1 = 1.f / l1;
    size_t ob0 = (size_t)(qb * 64 + wm * 16 + gid) * HID + (size_t)h * HDIM;
    size_t ob1 = ob0 + 8 * (size_t)HID;
#pragma unroll
    for (int nt = 0; nt < 16; nt++) {
        int col = nt * 8 + tig * 2;
        uint32_t hh, ll;
        split2(O[nt][0] * inv0, O[nt][1] * inv0, hh, ll);
        *(uint32_t*)&ahi_out[ob0 + col] = hh;
        *(uint32_t*)&alo_out[ob0 + col] = ll;
        split2(O[nt][2] * inv1, O[nt][3] * inv1, hh, ll);
        *(uint32_t*)&ahi_out[ob1 + col] = hh;
        *(uint32_t*)&alo_out[ob1 + col] = ll;
    }
}

// =====================================================================
// Host orchestration — multi-stream fork/join (graph-capturable)
// =====================================================================
static void convS(cudaStream_t st, const void* in, __nv_bfloat16* hi,
                  __nv_bfloat16* lo, size_t n) {
    int n8 = (int)(n / 8);
    int blocks = (n8 + 255) / 256;
    if (blocks > 6144) blocks = 6144;
    conv_split<<<blocks, 256, 0, st>>>((const float4*)in, hi, lo, n8);
}

#define SYM(v, s) cudaGetSymbolAddress((void**)&v, s)

extern "C" void kernel_launch(void* const* d_in, const int* in_sizes, int n_in,
                              void* d_out, int out_size)
{
    const float* hs     = (const float*)d_in[0];
    const float* cosp   = (const float*)d_in[1];
    const float* sinp   = (const float*)d_in[2];
    const float* bcos   = (const float*)d_in[3];
    const float* bsin   = (const float*)d_in[4];
    const int*   memidx = (const int*)d_in[5];
    const int*   imidx  = (const int*)d_in[6];
    const float* kc_in  = (const float*)d_in[7];
    const float* vc_in  = (const float*)d_in[8];
    const int*   blkoff = (const int*)d_in[9];
    const float* wqkv_w = (const float*)d_in[10];
    const float* wqkv_A = (const float*)d_in[11];
    const float* wqkv_B = (const float*)d_in[12];
    const float* wqkv_MA= (const float*)d_in[13];
    const float* wqkv_MB= (const float*)d_in[14];
    const float* wo_w   = (const float*)d_in[15];
    const float* wo_A   = (const float*)d_in[16];
    const float* wo_B   = (const float*)d_in[17];
    const float* wo_MA  = (const float*)d_in[18];
    const float* wo_MB  = (const float*)d_in[19];

    float* outp   = (float*)d_out;
    float* kc_out = outp + (size_t)TT * HID;
    float* vc_out = kc_out + CACHE_ELEMS;

    float *qkv;
    SYM(qkv, g_qkv);

    __nv_bfloat16 *hs_hi,*hs_lo,*attn_hi,*attn_lo,*q_hi,*q_lo,*k_hi,*k_lo,*v_hi,*v_lo;
    __nv_bfloat16 *tim_hi,*tim_lo,*tmem_hi,*tmem_lo;
    __nv_bfloat16 *wqkv_hi,*wqkv_lo,*wqA_hi,*wqA_lo,*wqB_hi,*wqB_lo,*wqMA_hi,*wqMA_lo,*wqMB_hi,*wqMB_lo;
    __nv_bfloat16 *wo_hi,*wo_lo,*woA_hi,*woA_lo,*woB_hi,*woB_lo,*woMA_hi,*woMA_lo,*woMB_hi,*woMB_lo;
    SYM(hs_hi, g_hs_hi);     SYM(hs_lo, g_hs_lo);
    SYM(attn_hi, g_attn_hi); SYM(attn_lo, g_attn_lo);
    SYM(q_hi, g_q_hi);       SYM(q_lo, g_q_lo);
    SYM(k_hi, g_k_hi);       SYM(k_lo, g_k_lo);
    SYM(v_hi, g_v_hi);       SYM(v_lo, g_v_lo);
    SYM(tim_hi, g_tim_hi);   SYM(tim_lo, g_tim_lo);
    SYM(tmem_hi, g_tmem_hi); SYM(tmem_lo, g_tmem_lo);
    SYM(wqkv_hi, g_wqkv_hi); SYM(wqkv_lo, g_wqkv_lo);
    SYM(wqA_hi, g_wqA_hi);   SYM(wqA_lo, g_wqA_lo);
    SYM(wqB_hi, g_wqB_hi);   SYM(wqB_lo, g_wqB_lo);
    SYM(wqMA_hi, g_wqMA_hi); SYM(wqMA_lo, g_wqMA_lo);
    SYM(wqMB_hi, g_wqMB_hi); SYM(wqMB_lo, g_wqMB_lo);
    SYM(wo_hi, g_wo_hi);     SYM(wo_lo, g_wo_lo);
    SYM(woA_hi, g_woA_hi);   SYM(woA_lo, g_woA_lo);
    SYM(woB_hi, g_woB_hi);   SYM(woB_lo, g_woB_lo);
    SYM(woMA_hi, g_woMA_hi); SYM(woMA_lo, g_woMA_lo);
    SYM(woMB_hi, g_woMB_hi); SYM(woMB_lo, g_woMB_lo);

    cudaFuncSetAttribute(gemm_hl, cudaFuncAttributeMaxDynamicSharedMemorySize, GEMM_SMEM);
    cudaFuncSetAttribute(flash_mma, cudaFuncAttributeMaxDynamicSharedMemorySize, FA3_SMEM);

    cudaStream_t s1, s2;
    cudaStreamCreateWithFlags(&s1, cudaStreamNonBlocking);
    cudaStreamCreateWithFlags(&s2, cudaStreamNonBlocking);
    cudaEvent_t eFork, eHs, eWqA, eWqB, eQKV, eCpy, eWoC, eLA, eLbM, eQall,
                eFlash, eWoA, eWOm, eS1, eS2;
    cudaEvent_t* evs[15] = {&eFork,&eHs,&eWqA,&eWqB,&eQKV,&eCpy,&eWoC,&eLA,&eLbM,
                            &eQall,&eFlash,&eWoA,&eWOm,&eS1,&eS2};
    for (int i = 0; i < 15; i++) cudaEventCreateWithFlags(evs[i], cudaEventDisableTiming);

    // ---- fork immediately: conversions run concurrently ----
    cudaEventRecord(eFork, 0);
    cudaStreamWaitEvent(s1, eFork, 0);
    cudaStreamWaitEvent(s2, eFork, 0);

    // origin: the big weight conversion (critical path for QKV gemm)
    convS(0, wqkv_w, wqkv_hi, wqkv_lo, (size_t)QKVO * HID);

    // s1: hs + LoRA-A/B weights concurrently with wqkv conv
    convS(s1, hs, hs_hi, hs_lo, (size_t)TT * HID);
    cudaEventRecord(eHs, s1);
    convS(s1, wqkv_A, wqA_hi, wqA_lo, (size_t)RANK * HID);
    convS(s1, wqkv_MA, wqMA_hi, wqMA_lo, (size_t)RANK * HID);
    cudaEventRecord(eWqA, s1);
    convS(s1, wqkv_B, wqB_hi, wqB_lo, (size_t)QKVO * RANK);
    convS(s1, wqkv_MB, wqMB_hi, wqMB_lo, (size_t)QKVO * RANK);
    cudaEventRecord(eWqB, s1);

    // origin: QKV main projection
    cudaStreamWaitEvent(0, eHs, 0);
    gemm_hl<<<dim3(QKVO/128, TT/128), 256, GEMM_SMEM>>>(hs_hi, hs_lo, wqkv_hi, wqkv_lo,
        qkv, nullptr, nullptr, TT, QKVO, HID, nullptr, nullptr);
    cudaEventRecord(eQKV, 0);

    // s1: cache memcpys + WO-side conversions
    cudaMemcpyAsync(kc_out, kc_in, (size_t)CACHE_ELEMS * sizeof(float),
                    cudaMemcpyDeviceToDevice, s1);
    cudaMemcpyAsync(vc_out, vc_in, (size_t)CACHE_ELEMS * sizeof(float),
                    cudaMemcpyDeviceToDevice, s1);
    cudaEventRecord(eCpy, s1);
    convS(s1, wo_w, wo_hi, wo_lo, (size_t)HID * HID);
    convS(s1, wo_A, woA_hi, woA_lo, (size_t)RANK * HID);
    convS(s1, wo_MA, woMA_hi, woMA_lo, (size_t)RANK * HID);
    convS(s1, wo_B, woB_hi, woB_lo, (size_t)HID * RANK);
    convS(s1, wo_MB, woMB_hi, woMB_lo, (size_t)HID * RANK);
    cudaEventRecord(eWoC, s1);

    // ---- s2: QKV LoRA-A (both), record eLA ----
    cudaStreamWaitEvent(s2, eWqA, 0);
    gemm_hl<<<dim3(RANK/128, NIM/128), 256, GEMM_SMEM, s2>>>(hs_hi, hs_lo, wqA_hi, wqA_lo,
        nullptr, tim_hi, tim_lo, NIM, RANK, HID, imidx, nullptr);
    gemm_hl<<<dim3(RANK/128, NMEM/128), 256, GEMM_SMEM, s2>>>(hs_hi, hs_lo, wqMA_hi, wqMA_lo,
        nullptr, tmem_hi, tmem_lo, NMEM, RANK, HID, memidx, nullptr);
    cudaEventRecord(eLA, s2);

    // ---- QKV LoRA-B concurrently: im on s2, mem on s1 ----
    cudaStreamWaitEvent(s2, eQKV, 0);
    cudaStreamWaitEvent(s2, eWqB, 0);
    gemm_hl<<<dim3(QKVO/128, NIM/128), 256, GEMM_SMEM, s2>>>(tim_hi, tim_lo, wqB_hi, wqB_lo,
        qkv, nullptr, nullptr, NIM, QKVO, RANK, nullptr, imidx);

    cudaStreamWaitEvent(s1, eLA, 0);
    cudaStreamWaitEvent(s1, eQKV, 0);
    gemm_hl<<<dim3(QKVO/128, NMEM/128), 256, GEMM_SMEM, s1>>>(tmem_hi, tmem_lo, wqMB_hi, wqMB_lo,
        qkv, nullptr, nullptr, NMEM, QKVO, RANK, nullptr, memidx);
    cudaEventRecord(eLbM, s1);
    cudaEventRecord(eS1, s1);

    // ---- s2: cache fill + rope (need both LoRA-B writers + memcpys) ----
    cudaStreamWaitEvent(s2, eLbM, 0);
    cudaStreamWaitEvent(s2, eCpy, 0);
    fill_cache_kernel<<<NMEM, dim3(64, 8), 0, s2>>>(qkv, memidx, blkoff, bcos, bsin, kc_out, vc_out);
    rope_convert<<<dim3(TT, 12), dim3(32, 4), 0, s2>>>(qkv, cosp, sinp, q_hi, q_lo, k_hi, k_lo, v_hi, v_lo);
    cudaEventRecord(eQall, s2);

    // ---- origin: flash attention (single launch, heavy-first) ----
    cudaStreamWaitEvent(0, eQall, 0);
    flash_mma<<<dim3(TT/64, NHEADS), 128, FA3_SMEM>>>(q_hi, q_lo, k_hi, k_lo,
        v_hi, v_lo, attn_hi, attn_lo);
    cudaEventRecord(eFlash, 0);

    // ---- s2: WO LoRA-A (both, overlaps WO main); later WO LoRA-B mem ----
    cudaStreamWaitEvent(s2, eFlash, 0);
    cudaStreamWaitEvent(s2, eWoC, 0);
    gemm_hl<<<dim3(RANK/128, NIM/128), 256, GEMM_SMEM, s2>>>(attn_hi, attn_lo, woA_hi, woA_lo,
        nullptr, tim_hi, tim_lo, NIM, RANK, HID, imidx, nullptr);
    gemm_hl<<<dim3(RANK/128, NMEM/128), 256, GEMM_SMEM, s2>>>(attn_hi, attn_lo, woMA_hi, woMA_lo,
        nullptr, tmem_hi, tmem_lo, NMEM, RANK, HID, memidx, nullptr);
    cudaEventRecord(eWoA, s2);

    // ---- origin: WO main projection ----
    cudaStreamWaitEvent(0, eWoC, 0);
    gemm_hl<<<dim3(HID/128, TT/128), 256, GEMM_SMEM>>>(attn_hi, attn_lo, wo_hi, wo_lo,
        outp, nullptr, nullptr, TT, HID, HID, nullptr, nullptr);
    cudaEventRecord(eWOm, 0);

    // ---- WO LoRA-B concurrently: im on s0, mem on s2 ----
    cudaStreamWaitEvent(0, eWoA, 0);
    gemm_hl<<<dim3(HID/128, NIM/128), 256, GEMM_SMEM>>>(tim_hi, tim_lo, woB_hi, woB_lo,
        outp, nullptr, nullptr, NIM, HID, RANK, nullptr, imidx);

    cudaStreamWaitEvent(s2, eWOm, 0);
    gemm_hl<<<dim3(HID/128, NMEM/128), 256, GEMM_SMEM, s2>>>(tmem_hi, tmem_lo, woMB_hi, woMB_lo,
        outp, nullptr, nullptr, NMEM, HID, RANK, nullptr, memidx);
    cudaEventRecord(eS2, s2);

    // ---- join forked streams back into origin ----
    cudaStreamWaitEvent(0, eS1, 0);
    cudaStreamWaitEvent(0, eS2, 0);

    cudaStreamCaptureStatus st = cudaStreamCaptureStatusNone;
    cudaStreamIsCapturing(0, &st);
    if (st == cudaStreamCaptureStatusNone) {
        for (int i = 0; i < 15; i++) cudaEventDestroy(*evs[i]);
        cudaStreamDestroy(s1);
        cudaStreamDestroy(s2);
    }
}